// round 5
// baseline (speedup 1.0000x reference)
#include <cuda_runtime.h>
#include <cuda_bf16.h>
#include <math.h>

typedef unsigned long long u64;
typedef unsigned int u32;

#define B_MAX 4
#define N_IN 25089      // 1 + 8*56*56
#define T_IN 8
#define H_IN 56
#define W_IN 56
#define QT 8
#define QH 28
#define QW 28
#define QN 6273         // 1 + 8*28*28
#define KT 8
#define KH 7
#define KW 7
#define KN 393          // 1 + 8*7*7
#define NKV 3201        // 1 + 8*20*20 gathered tokens per batch
#define ATTN_SCALE 0.102062072615965745f   // 1/sqrt(96)

// ---------------- scratch (device globals; no allocation) ----------------
__device__ float g_q [(size_t)B_MAX * N_IN * 192];
__device__ float g_k [(size_t)B_MAX * NKV * 192];
__device__ float g_v [(size_t)B_MAX * NKV * 192];
__device__ float g_qp[(size_t)B_MAX * 2 * QN * 96];
__device__ float g_kp[(size_t)B_MAX * 2 * KN * 96];
__device__ float g_vp[(size_t)B_MAX * 2 * KN * 96];
__device__ float g_ao[(size_t)B_MAX * QN * 192];

// ---------------- helpers ----------------
__device__ __forceinline__ int hw_from_idx(int i) {
    return (i < 2) ? i : 7 + ((i - 2) / 3) * 8 + ((i - 2) % 3);
}
__device__ __forceinline__ int idx_from_hw(int v) {
    return (v <= 1) ? v : 2 + ((v - 7) >> 3) * 3 + ((v - 7) & 7);
}
__device__ __forceinline__ u32 smem_u32(const void* p) {
    u32 a;
    asm("{ .reg .u64 t; cvta.to.shared.u64 t, %1; cvt.u32.u64 %0, t; }" : "=r"(a) : "l"(p));
    return a;
}

// ---------------- mma.sync helpers ----------------
__device__ __forceinline__ void ldm_x4(u32* r, u32 addr) {
    asm volatile("ldmatrix.sync.aligned.m8n8.x4.shared.b16 {%0,%1,%2,%3}, [%4];"
        : "=r"(r[0]), "=r"(r[1]), "=r"(r[2]), "=r"(r[3]) : "r"(addr));
}
__device__ __forceinline__ void ldm_x2(u32* r, u32 addr) {
    asm volatile("ldmatrix.sync.aligned.m8n8.x2.shared.b16 {%0,%1}, [%2];"
        : "=r"(r[0]), "=r"(r[1]) : "r"(addr));
}
__device__ __forceinline__ void ldm_x2t(u32* r, u32 addr) {
    asm volatile("ldmatrix.sync.aligned.m8n8.x2.trans.shared.b16 {%0,%1}, [%2];"
        : "=r"(r[0]), "=r"(r[1]) : "r"(addr));
}
__device__ __forceinline__ void mma_bf16(float* c, const u32* a, const u32* b) {
    asm volatile("mma.sync.aligned.m16n8k16.row.col.f32.bf16.bf16.f32 "
        "{%0,%1,%2,%3}, {%4,%5,%6,%7}, {%8,%9}, {%0,%1,%2,%3};"
        : "+f"(c[0]), "+f"(c[1]), "+f"(c[2]), "+f"(c[3])
        : "r"(a[0]), "r"(a[1]), "r"(a[2]), "r"(a[3]), "r"(b[0]), "r"(b[1]));
}
__device__ __forceinline__ void split_store(__nv_bfloat16* hi, __nv_bfloat16* lo,
                                            int idx, float2 v) {
    __nv_bfloat162 h = __floats2bfloat162_rn(v.x, v.y);
    __nv_bfloat162 l = __floats2bfloat162_rn(v.x - __bfloat162float(h.x),
                                             v.y - __bfloat162float(h.y));
    *(__nv_bfloat162*)(hi + idx) = h;
    *(__nv_bfloat162*)(lo + idx) = l;
}

// ============================================================================
// bf16-split tensor-core GEMM: out[M,192] = in[M,K] @ W[192,K]^T + bias
// io_mode 0: in=x (direct), out=g_q, K=96
// io_mode 1: in=g_ao, out=outp, K=192
// io_mode 2: in=x with NKV gather, out=g_k, K=96 (w/bias pre-offset by host)
// io_mode 3: same but out=g_v
// ============================================================================
#define GS_AH 0
#define GS_AL 10240
#define GS_BH 20480
#define GS_BL 35840
#define GEMM_SMEM 51200

__global__ void __launch_bounds__(256) gemm192_mma(
    const float* __restrict__ in_x, const float* __restrict__ w,
    const float* __restrict__ bias, float* __restrict__ outp,
    int M, int K, int io_mode)
{
    extern __shared__ char sm[];
    __nv_bfloat16* Ah = (__nv_bfloat16*)(sm + GS_AH);
    __nv_bfloat16* Al = (__nv_bfloat16*)(sm + GS_AL);
    __nv_bfloat16* Bh = (__nv_bfloat16*)(sm + GS_BH);
    __nv_bfloat16* Bl = (__nv_bfloat16*)(sm + GS_BL);
    u32 smb = smem_u32(sm);

    int tid = threadIdx.x;
    int warp = tid >> 5, lane = tid & 31;
    int wm = warp & 3;
    int wn = warp >> 2;
    int rm = wm * 32, cn = wn * 96;
    int r0 = blockIdx.x * 128;

    const float* in = (io_mode == 1) ? (const float*)g_ao : in_x;
    float* out = (io_mode == 0) ? (float*)g_q :
                 (io_mode == 1) ? outp :
                 (io_mode == 2) ? (float*)g_k : (float*)g_v;
    bool gather = (io_mode >= 2);

    float C[2][12][4];
    #pragma unroll
    for (int mt = 0; mt < 2; ++mt)
        #pragma unroll
        for (int nt = 0; nt < 12; ++nt)
            #pragma unroll
            for (int i = 0; i < 4; ++i) C[mt][nt][i] = 0.f;

    for (int kc = 0; kc < K; kc += 32) {
        __syncthreads();
        for (int l = tid; l < 128 * 16; l += 256) {
            int row = l >> 4, col = (l & 15) * 2;
            int r = r0 + row;
            float2 v = make_float2(0.f, 0.f);
            if (r < M) {
                size_t src;
                if (gather) {
                    int b = r / NKV, ci = r - b * NKV;
                    int n = 0;
                    if (ci > 0) {
                        int cc = ci - 1;
                        int it = cc / 400, rem = cc - it * 400;
                        int h = hw_from_idx(rem / 20), wv = hw_from_idx(rem % 20);
                        n = 1 + (it * H_IN + h) * W_IN + wv;
                    }
                    src = ((size_t)b * N_IN + n) * 96;
                } else {
                    src = (size_t)r * K;
                }
                v = *(const float2*)&in[src + kc + col];
            }
            split_store(Ah, Al, row * 40 + col, v);
        }
        for (int l = tid; l < 192 * 16; l += 256) {
            int row = l >> 4, col = (l & 15) * 2;
            float2 v = *(const float2*)&w[(size_t)row * K + kc + col];
            split_store(Bh, Bl, row * 40 + col, v);
        }
        __syncthreads();

        #pragma unroll
        for (int ks = 0; ks < 2; ++ks) {
            int k0 = ks * 16;
            u32 ah[2][4], al[2][4];
            #pragma unroll
            for (int mt = 0; mt < 2; ++mt) {
                u32 off = (u32)(rm + mt * 16 + (lane & 15)) * 80u
                        + (u32)(k0 + ((lane >> 4) << 3)) * 2u;
                ldm_x4(ah[mt], smb + GS_AH + off);
                ldm_x4(al[mt], smb + GS_AL + off);
            }
            #pragma unroll
            for (int nt = 0; nt < 12; ++nt) {
                u32 off = (u32)(cn + nt * 8 + (lane & 7)) * 80u
                        + (u32)(k0 + (((lane >> 3) & 1) << 3)) * 2u;
                u32 bh[2], bl[2];
                ldm_x2(bh, smb + GS_BH + off);
                ldm_x2(bl, smb + GS_BL + off);
                #pragma unroll
                for (int mt = 0; mt < 2; ++mt) {
                    mma_bf16(C[mt][nt], ah[mt], bh);
                    mma_bf16(C[mt][nt], ah[mt], bl);
                    mma_bf16(C[mt][nt], al[mt], bh);
                }
            }
        }
    }

    int gr = lane >> 2;
    int gc = (lane & 3) * 2;
    #pragma unroll
    for (int mt = 0; mt < 2; ++mt) {
        int row0 = r0 + rm + mt * 16 + gr;
        int row1 = row0 + 8;
        #pragma unroll
        for (int nt = 0; nt < 12; ++nt) {
            int col = cn + nt * 8 + gc;
            float b0 = bias[col], b1 = bias[col + 1];
            if (row0 < M) {
                float2 o = make_float2(C[mt][nt][0] + b0, C[mt][nt][1] + b1);
                *(float2*)&out[(size_t)row0 * 192 + col] = o;
            }
            if (row1 < M) {
                float2 o = make_float2(C[mt][nt][2] + b0, C[mt][nt][3] + b1);
                *(float2*)&out[(size_t)row1 * 192 + col] = o;
            }
        }
    }
}

// ---------------- LN helper (96 threads) ----------------
__device__ __forceinline__ float ln96(float val, const float* gg, const float* bb, int c,
                                      float* p1, float* p2, float* mv)
{
    float s1 = val, s2 = val * val;
    #pragma unroll
    for (int off = 16; off > 0; off >>= 1) {
        s1 += __shfl_xor_sync(0xffffffffu, s1, off);
        s2 += __shfl_xor_sync(0xffffffffu, s2, off);
    }
    int wid = c >> 5, lane = c & 31;
    if (lane == 0) { p1[wid] = s1; p2[wid] = s2; }
    __syncthreads();
    if (c == 0) {
        float t1 = p1[0] + p1[1] + p1[2];
        float t2 = p2[0] + p2[1] + p2[2];
        float mean = t1 / 96.f;
        float var  = t2 / 96.f - mean * mean;
        mv[0] = mean; mv[1] = rsqrtf(var + 1e-5f);
    }
    __syncthreads();
    return (val - mv[0]) * mv[1] * gg[c] + bb[c];
}

// ---------------- Q pool, patch-shared ----------------
__global__ void pool_q_kernel(const float* __restrict__ cw, const float* __restrict__ gg,
                              const float* __restrict__ bb)
{
    __shared__ float patch[72][96];
    __shared__ float p1[3], p2[3], mv[2];
    int o = blockIdx.x;
    int w2 = o % QW;
    int h2 = (o / QW) % QH;
    int head = (o / (QW * QH)) & 1;
    int b = o / (QW * QH * 2);
    int c = threadIdx.x;

    for (int sp = 0; sp < 72; ++sp) {
        int it = sp / 9, dh = (sp % 9) / 3, dw = sp % 3;
        int ih = 2 * h2 - 1 + dh, iw = 2 * w2 - 1 + dw;
        float v = 0.f;
        if (ih >= 0 && ih < H_IN && iw >= 0 && iw < W_IN) {
            int tok = (it * H_IN + ih) * W_IN + iw;
            v = g_q[((size_t)(b * N_IN + 1 + tok)) * 192 + head * 96 + c];
        }
        patch[sp][c] = v;
    }
    float wreg[27];
    #pragma unroll
    for (int t = 0; t < 27; ++t) wreg[t] = cw[c * 27 + t];
    __syncthreads();

    for (int t2 = 0; t2 < QT; ++t2) {
        float s = 0.f;
        #pragma unroll
        for (int dt = 0; dt < 3; ++dt) {
            int it = t2 + dt - 1;
            if (it < 0 || it >= T_IN) continue;
            #pragma unroll
            for (int dh = 0; dh < 3; ++dh)
                #pragma unroll
                for (int dw = 0; dw < 3; ++dw)
                    s = fmaf(wreg[(dt * 3 + dh) * 3 + dw],
                             patch[it * 9 + dh * 3 + dw][c], s);
        }
        float outv = ln96(s, gg, bb, c, p1, p2, mv);
        int n = 1 + (t2 * QH + h2) * QW + w2;
        g_qp[((size_t)((b * 2 + head) * QN) + n) * 96 + c] = outv;
        __syncthreads();
    }
}

__global__ void cls_q_kernel(const float* __restrict__ gg, const float* __restrict__ bb)
{
    __shared__ float p1[3], p2[3], mv[2];
    int head = blockIdx.x & 1, b = blockIdx.x >> 1;
    int c = threadIdx.x;
    float val = g_q[((size_t)b * N_IN) * 192 + head * 96 + c];
    float outv = ln96(val, gg, bb, c, p1, p2, mv);
    g_qp[((size_t)((b * 2 + head) * QN)) * 96 + c] = outv;
}

// ---------------- K/V pool + LN ----------------
__global__ void pool_kv_kernel(const float* __restrict__ cw, const float* __restrict__ gg,
                               const float* __restrict__ bb, int whichV)
{
    __shared__ float p1[3], p2[3], mv[2];
    int o    = blockIdx.x;
    int n    = o % KN;
    int head = (o / KN) & 1;
    int b    = o / (KN * 2);
    int c    = threadIdx.x;

    const float* src = whichV ? g_v : g_k;
    float* outp      = whichV ? g_vp : g_kp;

    float val;
    if (n == 0) {
        val = src[((size_t)b * NKV) * 192 + head * 96 + c];
    } else {
        int tn  = n - 1;
        int t2  = tn / (KH * KW);
        int rem = tn % (KH * KW);
        int h2  = rem / KW, w2 = rem % KW;
        float s = 0.f;
        #pragma unroll
        for (int dt = 0; dt < 3; ++dt) {
            int it = t2 + dt - 1;
            if (it < 0 || it >= T_IN) continue;
            #pragma unroll
            for (int dh = 0; dh < 3; ++dh) {
                int ih = h2 * 8 + dh - 1;
                if (ih < 0 || ih >= H_IN) continue;
                #pragma unroll
                for (int dw = 0; dw < 3; ++dw) {
                    int iw = w2 * 8 + dw - 1;
                    if (iw < 0 || iw >= W_IN) continue;
                    int ci = 1 + (it * 20 + idx_from_hw(ih)) * 20 + idx_from_hw(iw);
                    s = fmaf(cw[c * 27 + (dt * 3 + dh) * 3 + dw],
                             src[((size_t)(b * NKV + ci)) * 192 + head * 96 + c], s);
                }
            }
        }
        val = s;
    }
    float outv = ln96(val, gg, bb, c, p1, p2, mv);
    outp[((size_t)((b * 2 + head) * KN) + n) * 96 + c] = outv;
}

// ============================================================================
// fused attention on tensor cores: 32 q-rows / 256 threads / 8 warps
// warp = (warpm: 2 m-halves of 16 rows) x (warpn: 4 n-groups)
// QK: warp computes 16 rows x 16 keys (2 n-tiles); AV: 16 rows x 24 cols (3 n-tiles)
// ============================================================================
#define AT_QHI  0
#define AT_QLO  6656           // 32*104*2
#define AT_KHI  13312
#define AT_KLO  26624          // 64*104*2 each
#define AT_PHI  39936
#define AT_PLO  44544          // 32*72*2 each
#define AT_SREL 49152          // 32*24*4
#define AT_SSUM 52224          // 32*4
#define ATTN_SMEM 52480

__global__ void __launch_bounds__(256) attn_mma_kernel(
    const float* __restrict__ rph, const float* __restrict__ rpw,
    const float* __restrict__ rpt)
{
    extern __shared__ char sm[];
    __nv_bfloat16* Qhi = (__nv_bfloat16*)(sm + AT_QHI);
    __nv_bfloat16* Qlo = (__nv_bfloat16*)(sm + AT_QLO);
    __nv_bfloat16* Khi = (__nv_bfloat16*)(sm + AT_KHI);
    __nv_bfloat16* Klo = (__nv_bfloat16*)(sm + AT_KLO);
    __nv_bfloat16* Phi = (__nv_bfloat16*)(sm + AT_PHI);
    __nv_bfloat16* Plo = (__nv_bfloat16*)(sm + AT_PLO);
    float* srel = (float*)(sm + AT_SREL);
    float* ssum = (float*)(sm + AT_SSUM);
    u32 smb = smem_u32(sm);

    int tid = threadIdx.x;
    int warp = tid >> 5, lane = tid & 31;
    int warpm = warp & 1, warpn = warp >> 1;
    int gr = lane >> 2, gc = (lane & 3) * 2;
    int bh = blockIdx.y;
    int q0 = blockIdx.x * 32;
    const float* qp = g_qp + (size_t)bh * QN * 96;
    const float* kp = g_kp + (size_t)bh * KN * 96;
    const float* vp = g_vp + (size_t)bh * KN * 96;

    if (tid < 32) ssum[tid] = 0.f;

    // stage Q (hi/lo split), row-major stride 104
    for (int l = tid; l < 32 * 48; l += 256) {
        int row = l / 48, col = (l - row * 48) * 2;
        int qr = q0 + row;
        float2 v = (qr < QN) ? *(const float2*)&qp[(size_t)qr * 96 + col]
                             : make_float2(0.f, 0.f);
        split_store(Qhi, Qlo, row * 104 + col, v);
    }
    __syncthreads();

    // rel-pos dots (fp32 from hi+lo)
    for (int idx = tid; idx < 32 * 22; idx += 256) {
        int qi = idx / 22, r = idx - qi * 22;
        int qr = q0 + qi;
        float s = 0.f;
        if (qr > 0 && qr < QN) {
            int tok = qr - 1;
            int tq = tok / (QH * QW);
            int hq = (tok / QW) % QH;
            int wq = tok % QW;
            const float* tab;
            if (r < 8)       tab = rpt + (size_t)(tq - r + 7) * 96;
            else if (r < 15) tab = rph + (size_t)(hq - 4 * (r - 8) + 24) * 96;
            else             tab = rpw + (size_t)(wq - 4 * (r - 15) + 24) * 96;
            #pragma unroll 4
            for (int k = 0; k < 96; ++k) {
                float qv = __bfloat162float(Qhi[qi * 104 + k])
                         + __bfloat162float(Qlo[qi * 104 + k]);
                s = fmaf(qv, tab[k], s);
            }
        }
        srel[qi * 24 + r] = s;
    }

    float sumA = 0.f, sumB = 0.f;
    float C[3][4];
    #pragma unroll
    for (int nt = 0; nt < 3; ++nt)
        #pragma unroll
        for (int i = 0; i < 4; ++i) C[nt][i] = 0.f;

    for (int j0 = 0; j0 < 448; j0 += 64) {
        __syncthreads();
        // stage K chunk (hi/lo), row-major [jc][k] stride 104
        for (int l = tid; l < 64 * 48; l += 256) {
            int jc = l / 48, col = (l - jc * 48) * 2;
            int j = j0 + jc;
            float2 v = (j < KN) ? *(const float2*)&kp[(size_t)j * 96 + col]
                                : make_float2(0.f, 0.f);
            split_store(Khi, Klo, jc * 104 + col, v);
        }
        __syncthreads();

        // QK^T
        float S[2][4];
        #pragma unroll
        for (int nt = 0; nt < 2; ++nt)
            #pragma unroll
            for (int i = 0; i < 4; ++i) S[nt][i] = 0.f;
        #pragma unroll
        for (int ks = 0; ks < 6; ++ks) {
            int k0 = ks * 16;
            u32 offa = smb + AT_QHI + (u32)(warpm * 16 + (lane & 15)) * 208u
                     + (u32)(k0 + ((lane >> 4) << 3)) * 2u;
            u32 ah[4], al[4];
            ldm_x4(ah, offa);
            ldm_x4(al, offa + (AT_QLO - AT_QHI));
            #pragma unroll
            for (int nt = 0; nt < 2; ++nt) {
                u32 offb = smb + AT_KHI + (u32)(warpn * 16 + nt * 8 + (lane & 7)) * 208u
                         + (u32)(k0 + (((lane >> 3) & 1) << 3)) * 2u;
                u32 bhf[2], blf[2];
                ldm_x2(bhf, offb);
                ldm_x2(blf, offb + (AT_KLO - AT_KHI));
                mma_bf16(S[nt], ah, bhf);
                mma_bf16(S[nt], ah, blf);
                mma_bf16(S[nt], al, bhf);
            }
        }

        // scale + rel-pos + exp, write P (hi/lo), accumulate row sums
        #pragma unroll
        for (int nt = 0; nt < 2; ++nt) {
            #pragma unroll
            for (int half = 0; half < 2; ++half) {
                int qi = warpm * 16 + gr + half * 8;
                #pragma unroll
                for (int e = 0; e < 2; ++e) {
                    int j = j0 + warpn * 16 + nt * 8 + gc + e;
                    float ev = 0.f;
                    if (j < KN) {
                        float s = S[nt][half * 2 + e] * ATTN_SCALE;
                        if (j > 0) {
                            int kk = j - 1;
                            int kt = kk / 49, rm = kk - kt * 49;
                            int rh = rm / 7, rw = rm - rh * 7;
                            s += srel[qi * 24 + kt] + srel[qi * 24 + 8 + rh]
                               + srel[qi * 24 + 15 + rw];
                        }
                        ev = __expf(s);
                    }
                    if (half == 0) sumA += ev; else sumB += ev;
                    __nv_bfloat16 h = __float2bfloat16(ev);
                    int pidx = qi * 72 + (j - j0);
                    Phi[pidx] = h;
                    Plo[pidx] = __float2bfloat16(ev - __bfloat162float(h));
                }
            }
        }
        __syncthreads();
        // stage V chunk into K buffers
        for (int l = tid; l < 64 * 48; l += 256) {
            int jc = l / 48, col = (l - jc * 48) * 2;
            int j = j0 + jc;
            float2 v = (j < KN) ? *(const float2*)&vp[(size_t)j * 96 + col]
                                : make_float2(0.f, 0.f);
            split_store(Khi, Klo, jc * 104 + col, v);
        }
        __syncthreads();

        // AV: P [32 x 64] @ V [64 x 96]
        #pragma unroll
        for (int ks = 0; ks < 4; ++ks) {
            int k0 = ks * 16;
            u32 offp = smb + AT_PHI + (u32)(warpm * 16 + (lane & 15)) * 144u
                     + (u32)(k0 + ((lane >> 4) << 3)) * 2u;
            u32 ph[4], pl[4];
            ldm_x4(ph, offp);
            ldm_x4(pl, offp + (AT_PLO - AT_PHI));
            #pragma unroll
            for (int nt = 0; nt < 3; ++nt) {
                int c0 = warpn * 24 + nt * 8;
                u32 offv = smb + AT_KHI + (u32)(k0 + (lane & 15)) * 208u + (u32)c0 * 2u;
                u32 vh[2], vl[2];
                ldm_x2t(vh, offv);
                ldm_x2t(vl, offv + (AT_KLO - AT_KHI));
                mma_bf16(C[nt], ph, vh);
                mma_bf16(C[nt], ph, vl);
                mma_bf16(C[nt], pl, vh);
            }
        }
    }

    // reduce row sums within quads, merge across n-warps
    sumA += __shfl_xor_sync(0xffffffffu, sumA, 1);
    sumA += __shfl_xor_sync(0xffffffffu, sumA, 2);
    sumB += __shfl_xor_sync(0xffffffffu, sumB, 1);
    sumB += __shfl_xor_sync(0xffffffffu, sumB, 2);
    if ((lane & 3) == 0) {
        atomicAdd(&ssum[warpm * 16 + gr], sumA);
        atomicAdd(&ssum[warpm * 16 + 8 + gr], sumB);
    }
    __syncthreads();

    // epilogue: normalize + residual + store
    int b = bh >> 1, head = bh & 1;
    #pragma unroll
    for (int half = 0; half < 2; ++half) {
        int qi = warpm * 16 + gr + half * 8;
        int qr = q0 + qi;
        if (qr < QN) {
            float ri = 1.f / ssum[qi];
            #pragma unroll
            for (int nt = 0; nt < 3; ++nt) {
                int col = warpn * 24 + nt * 8 + gc;
                float q0v = __bfloat162float(Qhi[qi * 104 + col])
                          + __bfloat162float(Qlo[qi * 104 + col]);
                float q1v = __bfloat162float(Qhi[qi * 104 + col + 1])
                          + __bfloat162float(Qlo[qi * 104 + col + 1]);
                float2 o = make_float2(C[nt][half * 2 + 0] * ri + q0v,
                                       C[nt][half * 2 + 1] * ri + q1v);
                *(float2*)&g_ao[((size_t)(b * QN + qr)) * 192 + head * 96 + col] = o;
            }
        }
    }
}

// ---------------- launch ----------------
extern "C" void kernel_launch(void* const* d_in, const int* in_sizes, int n_in,
                              void* d_out, int out_size)
{
    const float* x      = (const float*)d_in[0];
    const float* qkv_w  = (const float*)d_in[1];
    const float* qkv_b  = (const float*)d_in[2];
    const float* proj_w = (const float*)d_in[3];
    const float* proj_b = (const float*)d_in[4];
    const float* pq_w   = (const float*)d_in[5];
    const float* nq_g   = (const float*)d_in[6];
    const float* nq_b   = (const float*)d_in[7];
    const float* pk_w   = (const float*)d_in[8];
    const float* nk_g   = (const float*)d_in[9];
    const float* nk_b   = (const float*)d_in[10];
    const float* pv_w   = (const float*)d_in[11];
    const float* nv_g   = (const float*)d_in[12];
    const float* nv_b   = (const float*)d_in[13];
    const float* rph    = (const float*)d_in[14];
    const float* rpw    = (const float*)d_in[15];
    const float* rpt    = (const float*)d_in[16];

    int B = in_sizes[0] / (N_IN * 96);
    if (B > B_MAX) B = B_MAX;
    int M   = B * N_IN;
    int Mkv = B * NKV;

    cudaFuncSetAttribute(gemm192_mma, cudaFuncAttributeMaxDynamicSharedMemorySize, GEMM_SMEM);
    cudaFuncSetAttribute(attn_mma_kernel, cudaFuncAttributeMaxDynamicSharedMemorySize, ATTN_SMEM);

    gemm192_mma<<<(M + 127) / 128, 256, GEMM_SMEM>>>(x, qkv_w, qkv_b, nullptr, M, 96, 0);
    gemm192_mma<<<(Mkv + 127) / 128, 256, GEMM_SMEM>>>(x, qkv_w + 192 * 96, qkv_b + 192,
                                                       nullptr, Mkv, 96, 2);
    gemm192_mma<<<(Mkv + 127) / 128, 256, GEMM_SMEM>>>(x, qkv_w + 384 * 96, qkv_b + 384,
                                                       nullptr, Mkv, 96, 3);
    pool_q_kernel <<<B * 2 * QH * QW, 96>>>(pq_w, nq_g, nq_b);
    cls_q_kernel  <<<B * 2, 96>>>(nq_g, nq_b);
    pool_kv_kernel<<<B * 2 * KN, 96>>>(pk_w, nk_g, nk_b, 0);
    pool_kv_kernel<<<B * 2 * KN, 96>>>(pv_w, nv_g, nv_b, 1);
    attn_mma_kernel<<<dim3((QN + 31) / 32, B * 2), 256, ATTN_SMEM>>>(rph, rpw, rpt);
    gemm192_mma<<<(B * QN + 127) / 128, 256, GEMM_SMEM>>>(nullptr, proj_w, proj_b,
                                                          (float*)d_out, B * QN, 192, 1);
}

// round 6
// speedup vs baseline: 1.1551x; 1.1551x over previous
#include <cuda_runtime.h>
#include <cuda_bf16.h>
#include <math.h>

typedef unsigned long long u64;
typedef unsigned int u32;

#define B_MAX 4
#define N_IN 25089      // 1 + 8*56*56
#define T_IN 8
#define H_IN 56
#define W_IN 56
#define QT 8
#define QH 28
#define QW 28
#define QN 6273         // 1 + 8*28*28
#define KT 8
#define KH 7
#define KW 7
#define KN 393          // 1 + 8*7*7
#define NKV 3201        // 1 + 8*20*20 gathered tokens per batch
#define ATTN_SCALE 0.102062072615965745f   // 1/sqrt(96)

// ---------------- scratch (device globals; no allocation) ----------------
__device__ float g_q [(size_t)B_MAX * N_IN * 192];
__device__ float g_k [(size_t)B_MAX * NKV * 192];
__device__ float g_v [(size_t)B_MAX * NKV * 192];
__device__ float g_qp[(size_t)B_MAX * 2 * QN * 96];
__device__ float g_kp[(size_t)B_MAX * 2 * KN * 96];
__device__ float g_vp[(size_t)B_MAX * 2 * KN * 96];
__device__ float g_ao[(size_t)B_MAX * QN * 192];

// ---------------- scalar helpers ----------------
__device__ __forceinline__ void fma2(u64& d, u64 a, u64 b) {
    asm("fma.rn.f32x2 %0, %1, %2, %0;" : "+l"(d) : "l"(a), "l"(b));
}
__device__ __forceinline__ u64 dupf(float v) {
    u64 r; asm("mov.b64 %0, {%1, %1};" : "=l"(r) : "f"(v)); return r;
}
__device__ __forceinline__ float2 u2f(u64 v) {
    float2 r; asm("mov.b64 {%0, %1}, %2;" : "=f"(r.x), "=f"(r.y) : "l"(v)); return r;
}
__device__ __forceinline__ int hw_from_idx(int i) {
    return (i < 2) ? i : 7 + ((i - 2) / 3) * 8 + ((i - 2) % 3);
}
__device__ __forceinline__ int idx_from_hw(int v) {
    return (v <= 1) ? v : 2 + ((v - 7) >> 3) * 3 + ((v - 7) & 7);
}
__device__ __forceinline__ u32 smem_u32(const void* p) {
    u32 a;
    asm("{ .reg .u64 t; cvta.to.shared.u64 t, %1; cvt.u32.u64 %0, t; }" : "=r"(a) : "l"(p));
    return a;
}

// ---------------- mma.sync helpers ----------------
__device__ __forceinline__ void ldm_x4(u32* r, u32 addr) {
    asm volatile("ldmatrix.sync.aligned.m8n8.x4.shared.b16 {%0,%1,%2,%3}, [%4];"
        : "=r"(r[0]), "=r"(r[1]), "=r"(r[2]), "=r"(r[3]) : "r"(addr));
}
__device__ __forceinline__ void ldm_x2(u32* r, u32 addr) {
    asm volatile("ldmatrix.sync.aligned.m8n8.x2.shared.b16 {%0,%1}, [%2];"
        : "=r"(r[0]), "=r"(r[1]) : "r"(addr));
}
__device__ __forceinline__ void mma_bf16(float* c, const u32* a, const u32* b) {
    asm volatile("mma.sync.aligned.m16n8k16.row.col.f32.bf16.bf16.f32 "
        "{%0,%1,%2,%3}, {%4,%5,%6,%7}, {%8,%9}, {%0,%1,%2,%3};"
        : "+f"(c[0]), "+f"(c[1]), "+f"(c[2]), "+f"(c[3])
        : "r"(a[0]), "r"(a[1]), "r"(a[2]), "r"(a[3]), "r"(b[0]), "r"(b[1]));
}
__device__ __forceinline__ void split_store(__nv_bfloat16* hi, __nv_bfloat16* lo,
                                            int idx, float2 v) {
    __nv_bfloat162 h = __floats2bfloat162_rn(v.x, v.y);
    __nv_bfloat162 l = __floats2bfloat162_rn(v.x - __bfloat162float(h.x),
                                             v.y - __bfloat162float(h.y));
    *(__nv_bfloat162*)(hi + idx) = h;
    *(__nv_bfloat162*)(lo + idx) = l;
}

// ============================================================================
// bf16-split tensor-core GEMM: out[M,192] = in[M,K] @ W[192,K]^T + bias
// io_mode 0: in=x (direct), out=g_q, K=96
// io_mode 1: in=g_ao, out=outp, K=192
// io_mode 2: merged KV: in=x with NKV gather; blockIdx.y: 0->K, 1->V
// ============================================================================
#define GS_AH 0
#define GS_AL 10240
#define GS_BH 20480
#define GS_BL 35840
#define GEMM_SMEM 51200

__global__ void __launch_bounds__(256) gemm192_mma(
    const float* __restrict__ in_x, const float* __restrict__ w,
    const float* __restrict__ bias, float* __restrict__ outp,
    int M, int K, int io_mode)
{
    extern __shared__ char sm[];
    __nv_bfloat16* Ah = (__nv_bfloat16*)(sm + GS_AH);
    __nv_bfloat16* Al = (__nv_bfloat16*)(sm + GS_AL);
    __nv_bfloat16* Bh = (__nv_bfloat16*)(sm + GS_BH);
    __nv_bfloat16* Bl = (__nv_bfloat16*)(sm + GS_BL);
    u32 smb = smem_u32(sm);

    int tid = threadIdx.x;
    int warp = tid >> 5, lane = tid & 31;
    int wm = warp & 3;
    int wn = warp >> 2;
    int rm = wm * 32, cn = wn * 96;
    int r0 = blockIdx.x * 128;

    const float* in = (io_mode == 1) ? (const float*)g_ao : in_x;
    const float* wp = w;
    const float* bp = bias;
    float* out;
    bool gather = false;
    if (io_mode == 0)      out = (float*)g_q;
    else if (io_mode == 1) out = outp;
    else {
        gather = true;
        int sel = blockIdx.y;
        wp = w + (size_t)(1 + sel) * 192 * 96;
        bp = bias + (1 + sel) * 192;
        out = sel ? (float*)g_v : (float*)g_k;
    }

    float C[2][12][4];
    #pragma unroll
    for (int mt = 0; mt < 2; ++mt)
        #pragma unroll
        for (int nt = 0; nt < 12; ++nt)
            #pragma unroll
            for (int i = 0; i < 4; ++i) C[mt][nt][i] = 0.f;

    for (int kc = 0; kc < K; kc += 32) {
        __syncthreads();
        for (int l = tid; l < 128 * 16; l += 256) {
            int row = l >> 4, col = (l & 15) * 2;
            int r = r0 + row;
            float2 v = make_float2(0.f, 0.f);
            if (r < M) {
                size_t src;
                if (gather) {
                    int b = r / NKV, ci = r - b * NKV;
                    int n = 0;
                    if (ci > 0) {
                        int cc = ci - 1;
                        int it = cc / 400, rem = cc - it * 400;
                        int h = hw_from_idx(rem / 20), wv = hw_from_idx(rem % 20);
                        n = 1 + (it * H_IN + h) * W_IN + wv;
                    }
                    src = ((size_t)b * N_IN + n) * 96;
                } else {
                    src = (size_t)r * K;
                }
                v = *(const float2*)&in[src + kc + col];
            }
            split_store(Ah, Al, row * 40 + col, v);
        }
        for (int l = tid; l < 192 * 16; l += 256) {
            int row = l >> 4, col = (l & 15) * 2;
            float2 v = *(const float2*)&wp[(size_t)row * K + kc + col];
            split_store(Bh, Bl, row * 40 + col, v);
        }
        __syncthreads();

        #pragma unroll
        for (int ks = 0; ks < 2; ++ks) {
            int k0 = ks * 16;
            u32 ah[2][4], al[2][4];
            #pragma unroll
            for (int mt = 0; mt < 2; ++mt) {
                u32 off = (u32)(rm + mt * 16 + (lane & 15)) * 80u
                        + (u32)(k0 + ((lane >> 4) << 3)) * 2u;
                ldm_x4(ah[mt], smb + GS_AH + off);
                ldm_x4(al[mt], smb + GS_AL + off);
            }
            #pragma unroll
            for (int nt = 0; nt < 12; ++nt) {
                u32 off = (u32)(cn + nt * 8 + (lane & 7)) * 80u
                        + (u32)(k0 + (((lane >> 3) & 1) << 3)) * 2u;
                u32 bh[2], bl[2];
                ldm_x2(bh, smb + GS_BH + off);
                ldm_x2(bl, smb + GS_BL + off);
                #pragma unroll
                for (int mt = 0; mt < 2; ++mt) {
                    mma_bf16(C[mt][nt], ah[mt], bh);
                    mma_bf16(C[mt][nt], ah[mt], bl);
                    mma_bf16(C[mt][nt], al[mt], bh);
                }
            }
        }
    }

    int gr = lane >> 2;
    int gc = (lane & 3) * 2;
    #pragma unroll
    for (int mt = 0; mt < 2; ++mt) {
        int row0 = r0 + rm + mt * 16 + gr;
        int row1 = row0 + 8;
        #pragma unroll
        for (int nt = 0; nt < 12; ++nt) {
            int col = cn + nt * 8 + gc;
            float b0 = bp[col], b1 = bp[col + 1];
            if (row0 < M) {
                float2 o = make_float2(C[mt][nt][0] + b0, C[mt][nt][1] + b1);
                *(float2*)&out[(size_t)row0 * 192 + col] = o;
            }
            if (row1 < M) {
                float2 o = make_float2(C[mt][nt][2] + b0, C[mt][nt][3] + b1);
                *(float2*)&out[(size_t)row1 * 192 + col] = o;
            }
        }
    }
}

// ---------------- LN helper (96 threads) ----------------
__device__ __forceinline__ float ln96(float val, const float* gg, const float* bb, int c,
                                      float* p1, float* p2, float* mv)
{
    float s1 = val, s2 = val * val;
    #pragma unroll
    for (int off = 16; off > 0; off >>= 1) {
        s1 += __shfl_xor_sync(0xffffffffu, s1, off);
        s2 += __shfl_xor_sync(0xffffffffu, s2, off);
    }
    int wid = c >> 5, lane = c & 31;
    if (lane == 0) { p1[wid] = s1; p2[wid] = s2; }
    __syncthreads();
    if (c == 0) {
        float t1 = p1[0] + p1[1] + p1[2];
        float t2 = p2[0] + p2[1] + p2[2];
        float mean = t1 / 96.f;
        float var  = t2 / 96.f - mean * mean;
        mv[0] = mean; mv[1] = rsqrtf(var + 1e-5f);
    }
    __syncthreads();
    return (val - mv[0]) * mv[1] * gg[c] + bb[c];
}

// ---------------- Q pool: register plane-sums, no smem patch; cls folded in ----------------
__global__ void pool_q_kernel(const float* __restrict__ cw, const float* __restrict__ gg,
                              const float* __restrict__ bb, int nSpatial)
{
    __shared__ float p1[3], p2[3], mv[2];
    int o = blockIdx.x;
    int c = threadIdx.x;

    if (o >= nSpatial) {   // cls token blocks
        int idx = o - nSpatial;
        int head = idx & 1, b = idx >> 1;
        float val = g_q[((size_t)b * N_IN) * 192 + head * 96 + c];
        float outv = ln96(val, gg, bb, c, p1, p2, mv);
        g_qp[((size_t)((b * 2 + head) * QN)) * 96 + c] = outv;
        return;
    }

    int w2 = o % QW;
    int h2 = (o / QW) % QH;
    int head = (o / (QW * QH)) & 1;
    int b = o / (QW * QH * 2);

    float wreg[27];
    #pragma unroll
    for (int t = 0; t < 27; ++t) wreg[t] = cw[c * 27 + t];

    // per-t-plane partial sums for each of the 3 dt weight slices
    float ps[8][3];
    #pragma unroll
    for (int it = 0; it < 8; ++it)
        #pragma unroll
        for (int d = 0; d < 3; ++d) ps[it][d] = 0.f;

    const float* base = g_q + ((size_t)(b * N_IN + 1)) * 192 + head * 96 + c;
    #pragma unroll
    for (int dh = 0; dh < 3; ++dh) {
        int ih = 2 * h2 - 1 + dh;
        if (ih < 0 || ih >= H_IN) continue;
        #pragma unroll
        for (int dw = 0; dw < 3; ++dw) {
            int iw = 2 * w2 - 1 + dw;
            if (iw < 0 || iw >= W_IN) continue;
            float w0 = wreg[(0 * 3 + dh) * 3 + dw];
            float w1 = wreg[(1 * 3 + dh) * 3 + dw];
            float w2r = wreg[(2 * 3 + dh) * 3 + dw];
            #pragma unroll
            for (int it = 0; it < 8; ++it) {
                int tok = (it * H_IN + ih) * W_IN + iw;
                float v = base[(size_t)tok * 192];
                ps[it][0] = fmaf(w0, v, ps[it][0]);
                ps[it][1] = fmaf(w1, v, ps[it][1]);
                ps[it][2] = fmaf(w2r, v, ps[it][2]);
            }
        }
    }

    for (int t2 = 0; t2 < QT; ++t2) {
        float s = ps[t2][1];
        if (t2 > 0) s += ps[t2 - 1][0];
        if (t2 < 7) s += ps[t2 + 1][2];
        float outv = ln96(s, gg, bb, c, p1, p2, mv);
        int n = 1 + (t2 * QH + h2) * QW + w2;
        g_qp[((size_t)((b * 2 + head) * QN) + n) * 96 + c] = outv;
        __syncthreads();
    }
}

// ---------------- K/V pool + LN, merged K/V via blockIdx.y ----------------
__global__ void pool_kv_kernel(const float* __restrict__ cwk, const float* __restrict__ ggk,
                               const float* __restrict__ bbk,
                               const float* __restrict__ cwv, const float* __restrict__ ggv,
                               const float* __restrict__ bbv)
{
    __shared__ float p1[3], p2[3], mv[2];
    int whichV = blockIdx.y;
    const float* cw = whichV ? cwv : cwk;
    const float* gg = whichV ? ggv : ggk;
    const float* bb = whichV ? bbv : bbk;
    int o    = blockIdx.x;
    int n    = o % KN;
    int head = (o / KN) & 1;
    int b    = o / (KN * 2);
    int c    = threadIdx.x;

    const float* src = whichV ? g_v : g_k;
    float* outp      = whichV ? g_vp : g_kp;

    float val;
    if (n == 0) {
        val = src[((size_t)b * NKV) * 192 + head * 96 + c];
    } else {
        int tn  = n - 1;
        int t2  = tn / (KH * KW);
        int rem = tn % (KH * KW);
        int h2  = rem / KW, w2 = rem % KW;
        float s = 0.f;
        #pragma unroll
        for (int dt = 0; dt < 3; ++dt) {
            int it = t2 + dt - 1;
            if (it < 0 || it >= T_IN) continue;
            #pragma unroll
            for (int dh = 0; dh < 3; ++dh) {
                int ih = h2 * 8 + dh - 1;
                if (ih < 0 || ih >= H_IN) continue;
                #pragma unroll
                for (int dw = 0; dw < 3; ++dw) {
                    int iw = w2 * 8 + dw - 1;
                    if (iw < 0 || iw >= W_IN) continue;
                    int ci = 1 + (it * 20 + idx_from_hw(ih)) * 20 + idx_from_hw(iw);
                    s = fmaf(cw[c * 27 + (dt * 3 + dh) * 3 + dw],
                             src[((size_t)(b * NKV + ci)) * 192 + head * 96 + c], s);
                }
            }
        }
        val = s;
    }
    float outv = ln96(val, gg, bb, c, p1, p2, mv);
    outp[((size_t)((b * 2 + head) * KN) + n) * 96 + c] = outv;
}

// ---------------- fused attention (R4 scalar version, 32 q-rows / 256 threads) ----------------
#define ATTN_SMEM 63488
#define AT_QSD  0                 // [96][66] dup'd q
#define AT_KBUF 6336              // K: [96][68] / V: [64][98]
#define AT_ES   12864             // [64][34] exp scores
#define AT_SREL 15040             // [32][24]
#define AT_RINV 15808             // [32]

__global__ void __launch_bounds__(256) attn_kernel(
    const float* __restrict__ rph, const float* __restrict__ rpw,
    const float* __restrict__ rpt)
{
    extern __shared__ float smf[];
    float* qs_d = smf + AT_QSD;
    float* kbuf = smf + AT_KBUF;
    float* es_t = smf + AT_ES;
    float* srel = smf + AT_SREL;
    float* rinv = smf + AT_RINV;

    int tid = threadIdx.x;   // 256
    int bh  = blockIdx.y;
    int q0  = blockIdx.x * 32;
    const float* qp = g_qp + (size_t)bh * QN * 96;
    const float* kp = g_kp + (size_t)bh * KN * 96;
    const float* vp = g_vp + (size_t)bh * KN * 96;

    for (int l = tid; l < 32 * 96; l += 256) {
        int qi = l / 96, k = l - qi * 96;
        int qr = q0 + qi;
        float v = (qr < QN) ? qp[(size_t)qr * 96 + k] : 0.f;
        qs_d[k * 66 + 2 * qi]     = v;
        qs_d[k * 66 + 2 * qi + 1] = v;
    }
    __syncthreads();

    for (int idx = tid; idx < 32 * 22; idx += 256) {
        int qi = idx / 22, r = idx - qi * 22;
        int qr = q0 + qi;
        float s = 0.f;
        if (qr > 0 && qr < QN) {
            int tok = qr - 1;
            int tq = tok / (QH * QW);
            int hq = (tok / QW) % QH;
            int wq = tok % QW;
            const float* tab;
            if (r < 8)       tab = rpt + (size_t)(tq - r + 7) * 96;
            else if (r < 15) tab = rph + (size_t)(hq - 4 * (r - 8) + 24) * 96;
            else             tab = rpw + (size_t)(wq - 4 * (r - 15) + 24) * 96;
            #pragma unroll 4
            for (int k = 0; k < 96; ++k) s = fmaf(qs_d[k * 66 + 2 * qi], tab[k], s);
        }
        srel[qi * 24 + r] = s;
    }

    int qi2 = tid >> 4;
    int jg  = tid & 15;
    int rA  = 2 * qi2;
    int c0  = jg * 6;
    float sumA = 0.f, sumB = 0.f;
    u64 acc[6];
    #pragma unroll
    for (int m = 0; m < 6; ++m) acc[m] = 0ull;

    for (int j0 = 0; j0 < KN; j0 += 64) {
        __syncthreads();
        for (int l = tid; l < 64 * 96; l += 256) {
            int jc = l / 96, k = l - jc * 96;
            int j = j0 + jc;
            kbuf[k * 68 + jc] = (j < KN) ? kp[(size_t)j * 96 + k] : 0.f;
        }
        __syncthreads();
        u64 d00 = 0ull, d01 = 0ull, d10 = 0ull, d11 = 0ull;
        #pragma unroll 4
        for (int k = 0; k < 96; ++k) {
            u64 a0 = *(const u64*)&qs_d[k * 66 + 2 * rA];
            u64 a1 = *(const u64*)&qs_d[k * 66 + 2 * rA + 2];
            u64 b0 = *(const u64*)&kbuf[k * 68 + jg * 4];
            u64 b1 = *(const u64*)&kbuf[k * 68 + jg * 4 + 2];
            fma2(d00, a0, b0); fma2(d01, a0, b1);
            fma2(d10, a1, b0); fma2(d11, a1, b1);
        }
        {
            float2 A0 = u2f(d00), A1 = u2f(d01), B0 = u2f(d10), B1 = u2f(d11);
            float sAv[4] = {A0.x, A0.y, A1.x, A1.y};
            float sBv[4] = {B0.x, B0.y, B1.x, B1.y};
            #pragma unroll
            for (int q = 0; q < 4; ++q) {
                int jc = jg * 4 + q;
                int j = j0 + jc;
                float eA = 0.f, eB = 0.f;
                if (j < KN) {
                    float sA = sAv[q] * ATTN_SCALE, sB = sBv[q] * ATTN_SCALE;
                    if (j > 0) {
                        int kk = j - 1;
                        int kt = kk / 49, rm = kk - kt * 49;
                        int rh = rm / 7,  rw = rm - rh * 7;
                        sA += srel[rA * 24 + kt] + srel[rA * 24 + 8 + rh] + srel[rA * 24 + 15 + rw];
                        sB += srel[(rA + 1) * 24 + kt] + srel[(rA + 1) * 24 + 8 + rh] + srel[(rA + 1) * 24 + 15 + rw];
                    }
                    eA = __expf(sA); eB = __expf(sB);
                }
                *(float2*)&es_t[jc * 34 + rA] = make_float2(eA, eB);
                sumA += eA; sumB += eB;
            }
        }
        __syncthreads();
        for (int l = tid; l < 64 * 96; l += 256) {
            int jc = l / 96, c = l - jc * 96;
            int j = j0 + jc;
            kbuf[jc * 98 + c] = (j < KN) ? vp[(size_t)j * 96 + c] : 0.f;
        }
        __syncthreads();
        #pragma unroll 2
        for (int jc = 0; jc < 64; ++jc) {
            u64 pp = *(const u64*)&es_t[jc * 34 + rA];
            const float* vrow = &kbuf[jc * 98 + c0];
            float2 v01 = *(const float2*)&vrow[0];
            float2 v23 = *(const float2*)&vrow[2];
            float2 v45 = *(const float2*)&vrow[4];
            fma2(acc[0], pp, dupf(v01.x));
            fma2(acc[1], pp, dupf(v01.y));
            fma2(acc[2], pp, dupf(v23.x));
            fma2(acc[3], pp, dupf(v23.y));
            fma2(acc[4], pp, dupf(v45.x));
            fma2(acc[5], pp, dupf(v45.y));
        }
    }
    #pragma unroll
    for (int off = 8; off > 0; off >>= 1) {
        sumA += __shfl_xor_sync(0xffffffffu, sumA, off, 16);
        sumB += __shfl_xor_sync(0xffffffffu, sumB, off, 16);
    }
    if (jg == 0) { rinv[rA] = 1.f / sumA; rinv[rA + 1] = 1.f / sumB; }
    __syncthreads();

    float iA = rinv[rA], iB = rinv[rA + 1];
    int b = bh >> 1, head = bh & 1;
    int gA = q0 + rA, gB = gA + 1;
    #pragma unroll
    for (int m = 0; m < 6; ++m) {
        float2 v = u2f(acc[m]);
        if (gA < QN)
            g_ao[((size_t)(b * QN + gA)) * 192 + head * 96 + c0 + m] =
                v.x * iA + qs_d[(c0 + m) * 66 + 2 * rA];
        if (gB < QN)
            g_ao[((size_t)(b * QN + gB)) * 192 + head * 96 + c0 + m] =
                v.y * iB + qs_d[(c0 + m) * 66 + 2 * rA + 2];
    }
}

// ---------------- launch ----------------
extern "C" void kernel_launch(void* const* d_in, const int* in_sizes, int n_in,
                              void* d_out, int out_size)
{
    const float* x      = (const float*)d_in[0];
    const float* qkv_w  = (const float*)d_in[1];
    const float* qkv_b  = (const float*)d_in[2];
    const float* proj_w = (const float*)d_in[3];
    const float* proj_b = (const float*)d_in[4];
    const float* pq_w   = (const float*)d_in[5];
    const float* nq_g   = (const float*)d_in[6];
    const float* nq_b   = (const float*)d_in[7];
    const float* pk_w   = (const float*)d_in[8];
    const float* nk_g   = (const float*)d_in[9];
    const float* nk_b   = (const float*)d_in[10];
    const float* pv_w   = (const float*)d_in[11];
    const float* nv_g   = (const float*)d_in[12];
    const float* nv_b   = (const float*)d_in[13];
    const float* rph    = (const float*)d_in[14];
    const float* rpw    = (const float*)d_in[15];
    const float* rpt    = (const float*)d_in[16];

    int B = in_sizes[0] / (N_IN * 96);
    if (B > B_MAX) B = B_MAX;
    int M   = B * N_IN;
    int Mkv = B * NKV;

    cudaFuncSetAttribute(gemm192_mma, cudaFuncAttributeMaxDynamicSharedMemorySize, GEMM_SMEM);
    cudaFuncSetAttribute(attn_kernel, cudaFuncAttributeMaxDynamicSharedMemorySize, ATTN_SMEM);

    gemm192_mma<<<(M + 127) / 128, 256, GEMM_SMEM>>>(x, qkv_w, qkv_b, nullptr, M, 96, 0);
    gemm192_mma<<<dim3((Mkv + 127) / 128, 2), 256, GEMM_SMEM>>>(x, qkv_w, qkv_b,
                                                                nullptr, Mkv, 96, 2);
    int nSpatial = B * 2 * QH * QW;
    pool_q_kernel<<<nSpatial + B * 2, 96>>>(pq_w, nq_g, nq_b, nSpatial);
    pool_kv_kernel<<<dim3(B * 2 * KN, 2), 96>>>(pk_w, nk_g, nk_b, pv_w, nv_g, nv_b);
    attn_kernel<<<dim3((QN + 31) / 32, B * 2), 256, ATTN_SMEM>>>(rph, rpw, rpt);
    gemm192_mma<<<(B * QN + 127) / 128, 256, GEMM_SMEM>>>(nullptr, proj_w, proj_b,
                                                          (float*)d_out, B * QN, 192, 1);
}

// round 8
// speedup vs baseline: 1.4340x; 1.2414x over previous
#include <cuda_runtime.h>
#include <cuda_bf16.h>
#include <math.h>

typedef unsigned long long u64;
typedef unsigned int u32;

#define B_MAX 4
#define N_IN 25089      // 1 + 8*56*56
#define T_IN 8
#define H_IN 56
#define W_IN 56
#define QT 8
#define QH 28
#define QW 28
#define QN 6273         // 1 + 8*28*28
#define KT 8
#define KH 7
#define KW 7
#define KN 393          // 1 + 8*7*7
#define NKV 3201        // 1 + 8*20*20 gathered tokens per batch
#define ATTN_SCALE 0.102062072615965745f   // 1/sqrt(96)

// ---------------- scratch (device globals; no allocation) ----------------
__device__ float g_q [(size_t)B_MAX * N_IN * 192];
__device__ float g_k [(size_t)B_MAX * NKV * 192];
__device__ float g_v [(size_t)B_MAX * NKV * 192];
__device__ float g_qp[(size_t)B_MAX * 2 * QN * 96];
__device__ float g_kp[(size_t)B_MAX * 2 * KN * 96];
__device__ float g_vp[(size_t)B_MAX * 2 * KN * 96];
__device__ float g_ao[(size_t)B_MAX * QN * 192];

// ---------------- helpers ----------------
__device__ __forceinline__ int hw_from_idx(int i) {
    return (i < 2) ? i : 7 + ((i - 2) / 3) * 8 + ((i - 2) % 3);
}
__device__ __forceinline__ int idx_from_hw(int v) {
    return (v <= 1) ? v : 2 + ((v - 7) >> 3) * 3 + ((v - 7) & 7);
}
__device__ __forceinline__ u32 smem_u32(const void* p) {
    u32 a;
    asm("{ .reg .u64 t; cvta.to.shared.u64 t, %1; cvt.u32.u64 %0, t; }" : "=r"(a) : "l"(p));
    return a;
}

// ---------------- mma.sync helpers ----------------
__device__ __forceinline__ void ldm_x4(u32* r, u32 addr) {
    asm volatile("ldmatrix.sync.aligned.m8n8.x4.shared.b16 {%0,%1,%2,%3}, [%4];"
        : "=r"(r[0]), "=r"(r[1]), "=r"(r[2]), "=r"(r[3]) : "r"(addr));
}
__device__ __forceinline__ void ldm_x2(u32* r, u32 addr) {
    asm volatile("ldmatrix.sync.aligned.m8n8.x2.shared.b16 {%0,%1}, [%2];"
        : "=r"(r[0]), "=r"(r[1]) : "r"(addr));
}
__device__ __forceinline__ void ldm_x4t(u32* r, u32 addr) {
    asm volatile("ldmatrix.sync.aligned.m8n8.x4.trans.shared.b16 {%0,%1,%2,%3}, [%4];"
        : "=r"(r[0]), "=r"(r[1]), "=r"(r[2]), "=r"(r[3]) : "r"(addr));
}
__device__ __forceinline__ void mma_bf16(float* c, const u32* a, const u32* b) {
    asm volatile("mma.sync.aligned.m16n8k16.row.col.f32.bf16.bf16.f32 "
        "{%0,%1,%2,%3}, {%4,%5,%6,%7}, {%8,%9}, {%0,%1,%2,%3};"
        : "+f"(c[0]), "+f"(c[1]), "+f"(c[2]), "+f"(c[3])
        : "r"(a[0]), "r"(a[1]), "r"(a[2]), "r"(a[3]), "r"(b[0]), "r"(b[1]));
}
__device__ __forceinline__ void split_store(__nv_bfloat16* hi, __nv_bfloat16* lo,
                                            int idx, float2 v) {
    __nv_bfloat162 h = __floats2bfloat162_rn(v.x, v.y);
    __nv_bfloat162 l = __floats2bfloat162_rn(v.x - __bfloat162float(h.x),
                                             v.y - __bfloat162float(h.y));
    *(__nv_bfloat162*)(hi + idx) = h;
    *(__nv_bfloat162*)(lo + idx) = l;
}
__device__ __forceinline__ u32 pack_hi(float a, float b, u32& lo) {
    __nv_bfloat162 h = __floats2bfloat162_rn(a, b);
    __nv_bfloat162 l = __floats2bfloat162_rn(a - __bfloat162float(h.x),
                                             b - __bfloat162float(h.y));
    lo = *(u32*)&l;
    return *(u32*)&h;
}

// ============================================================================
// bf16-split tensor-core GEMM: out[M,192] = in[M,K] @ W[192,K]^T + bias
// io_mode 0: in=x (direct), out=g_q, K=96
// io_mode 1: in=g_ao, out=outp, K=192
// io_mode 2: merged KV: in=x with NKV gather; blockIdx.y: 0->K, 1->V
// ============================================================================
#define GS_AH 0
#define GS_AL 10240
#define GS_BH 20480
#define GS_BL 35840
#define GEMM_SMEM 51200

__global__ void __launch_bounds__(256) gemm192_mma(
    const float* __restrict__ in_x, const float* __restrict__ w,
    const float* __restrict__ bias, float* __restrict__ outp,
    int M, int K, int io_mode)
{
    extern __shared__ char sm[];
    __nv_bfloat16* Ah = (__nv_bfloat16*)(sm + GS_AH);
    __nv_bfloat16* Al = (__nv_bfloat16*)(sm + GS_AL);
    __nv_bfloat16* Bh = (__nv_bfloat16*)(sm + GS_BH);
    __nv_bfloat16* Bl = (__nv_bfloat16*)(sm + GS_BL);
    u32 smb = smem_u32(sm);

    int tid = threadIdx.x;
    int warp = tid >> 5, lane = tid & 31;
    int wm = warp & 3;
    int wn = warp >> 2;
    int rm = wm * 32, cn = wn * 96;
    int r0 = blockIdx.x * 128;

    const float* in = (io_mode == 1) ? (const float*)g_ao : in_x;
    const float* wp = w;
    const float* bp = bias;
    float* out;
    bool gather = false;
    if (io_mode == 0)      out = (float*)g_q;
    else if (io_mode == 1) out = outp;
    else {
        gather = true;
        int sel = blockIdx.y;
        wp = w + (size_t)(1 + sel) * 192 * 96;
        bp = bias + (1 + sel) * 192;
        out = sel ? (float*)g_v : (float*)g_k;
    }

    float C[2][12][4];
    #pragma unroll
    for (int mt = 0; mt < 2; ++mt)
        #pragma unroll
        for (int nt = 0; nt < 12; ++nt)
            #pragma unroll
            for (int i = 0; i < 4; ++i) C[mt][nt][i] = 0.f;

    for (int kc = 0; kc < K; kc += 32) {
        __syncthreads();
        for (int l = tid; l < 128 * 16; l += 256) {
            int row = l >> 4, col = (l & 15) * 2;
            int r = r0 + row;
            float2 v = make_float2(0.f, 0.f);
            if (r < M) {
                size_t src;
                if (gather) {
                    int b = r / NKV, ci = r - b * NKV;
                    int n = 0;
                    if (ci > 0) {
                        int cc = ci - 1;
                        int it = cc / 400, rem = cc - it * 400;
                        int h = hw_from_idx(rem / 20), wv = hw_from_idx(rem % 20);
                        n = 1 + (it * H_IN + h) * W_IN + wv;
                    }
                    src = ((size_t)b * N_IN + n) * 96;
                } else {
                    src = (size_t)r * K;
                }
                v = *(const float2*)&in[src + kc + col];
            }
            split_store(Ah, Al, row * 40 + col, v);
        }
        for (int l = tid; l < 192 * 16; l += 256) {
            int row = l >> 4, col = (l & 15) * 2;
            float2 v = *(const float2*)&wp[(size_t)row * K + kc + col];
            split_store(Bh, Bl, row * 40 + col, v);
        }
        __syncthreads();

        #pragma unroll
        for (int ks = 0; ks < 2; ++ks) {
            int k0 = ks * 16;
            u32 ah[2][4], al[2][4];
            #pragma unroll
            for (int mt = 0; mt < 2; ++mt) {
                u32 off = (u32)(rm + mt * 16 + (lane & 15)) * 80u
                        + (u32)(k0 + ((lane >> 4) << 3)) * 2u;
                ldm_x4(ah[mt], smb + GS_AH + off);
                ldm_x4(al[mt], smb + GS_AL + off);
            }
            #pragma unroll
            for (int nt = 0; nt < 12; ++nt) {
                u32 off = (u32)(cn + nt * 8 + (lane & 7)) * 80u
                        + (u32)(k0 + (((lane >> 3) & 1) << 3)) * 2u;
                u32 bh[2], bl[2];
                ldm_x2(bh, smb + GS_BH + off);
                ldm_x2(bl, smb + GS_BL + off);
                #pragma unroll
                for (int mt = 0; mt < 2; ++mt) {
                    mma_bf16(C[mt][nt], ah[mt], bh);
                    mma_bf16(C[mt][nt], ah[mt], bl);
                    mma_bf16(C[mt][nt], al[mt], bh);
                }
            }
        }
    }

    int gr = lane >> 2;
    int gc = (lane & 3) * 2;
    #pragma unroll
    for (int mt = 0; mt < 2; ++mt) {
        int row0 = r0 + rm + mt * 16 + gr;
        int row1 = row0 + 8;
        #pragma unroll
        for (int nt = 0; nt < 12; ++nt) {
            int col = cn + nt * 8 + gc;
            float b0 = bp[col], b1 = bp[col + 1];
            if (row0 < M) {
                float2 o = make_float2(C[mt][nt][0] + b0, C[mt][nt][1] + b1);
                *(float2*)&out[(size_t)row0 * 192 + col] = o;
            }
            if (row1 < M) {
                float2 o = make_float2(C[mt][nt][2] + b0, C[mt][nt][3] + b1);
                *(float2*)&out[(size_t)row1 * 192 + col] = o;
            }
        }
    }
}

// ---------------- LN helper (96 threads) ----------------
__device__ __forceinline__ float ln96(float val, const float* gg, const float* bb, int c,
                                      float* p1, float* p2, float* mv)
{
    float s1 = val, s2 = val * val;
    #pragma unroll
    for (int off = 16; off > 0; off >>= 1) {
        s1 += __shfl_xor_sync(0xffffffffu, s1, off);
        s2 += __shfl_xor_sync(0xffffffffu, s2, off);
    }
    int wid = c >> 5, lane = c & 31;
    if (lane == 0) { p1[wid] = s1; p2[wid] = s2; }
    __syncthreads();
    if (c == 0) {
        float t1 = p1[0] + p1[1] + p1[2];
        float t2 = p2[0] + p2[1] + p2[2];
        float mean = t1 / 96.f;
        float var  = t2 / 96.f - mean * mean;
        mv[0] = mean; mv[1] = rsqrtf(var + 1e-5f);
    }
    __syncthreads();
    return (val - mv[0]) * mv[1] * gg[c] + bb[c];
}

// ---------------- Q pool: register plane-sums; cls folded in ----------------
__global__ void pool_q_kernel(const float* __restrict__ cw, const float* __restrict__ gg,
                              const float* __restrict__ bb, int nSpatial)
{
    __shared__ float p1[3], p2[3], mv[2];
    int o = blockIdx.x;
    int c = threadIdx.x;

    if (o >= nSpatial) {
        int idx = o - nSpatial;
        int head = idx & 1, b = idx >> 1;
        float val = g_q[((size_t)b * N_IN) * 192 + head * 96 + c];
        float outv = ln96(val, gg, bb, c, p1, p2, mv);
        g_qp[((size_t)((b * 2 + head) * QN)) * 96 + c] = outv;
        return;
    }

    int w2 = o % QW;
    int h2 = (o / QW) % QH;
    int head = (o / (QW * QH)) & 1;
    int b = o / (QW * QH * 2);

    float wreg[27];
    #pragma unroll
    for (int t = 0; t < 27; ++t) wreg[t] = cw[c * 27 + t];

    float ps[8][3];
    #pragma unroll
    for (int it = 0; it < 8; ++it)
        #pragma unroll
        for (int d = 0; d < 3; ++d) ps[it][d] = 0.f;

    const float* base = g_q + ((size_t)(b * N_IN + 1)) * 192 + head * 96 + c;
    #pragma unroll
    for (int dh = 0; dh < 3; ++dh) {
        int ih = 2 * h2 - 1 + dh;
        if (ih < 0 || ih >= H_IN) continue;
        #pragma unroll
        for (int dw = 0; dw < 3; ++dw) {
            int iw = 2 * w2 - 1 + dw;
            if (iw < 0 || iw >= W_IN) continue;
            float w0 = wreg[(0 * 3 + dh) * 3 + dw];
            float w1 = wreg[(1 * 3 + dh) * 3 + dw];
            float w2r = wreg[(2 * 3 + dh) * 3 + dw];
            #pragma unroll
            for (int it = 0; it < 8; ++it) {
                int tok = (it * H_IN + ih) * W_IN + iw;
                float v = base[(size_t)tok * 192];
                ps[it][0] = fmaf(w0, v, ps[it][0]);
                ps[it][1] = fmaf(w1, v, ps[it][1]);
                ps[it][2] = fmaf(w2r, v, ps[it][2]);
            }
        }
    }

    for (int t2 = 0; t2 < QT; ++t2) {
        float s = ps[t2][1];
        if (t2 > 0) s += ps[t2 - 1][0];
        if (t2 < 7) s += ps[t2 + 1][2];
        float outv = ln96(s, gg, bb, c, p1, p2, mv);
        int n = 1 + (t2 * QH + h2) * QW + w2;
        g_qp[((size_t)((b * 2 + head) * QN) + n) * 96 + c] = outv;
        __syncthreads();
    }
}

// ---------------- K/V pool + LN, merged via blockIdx.y ----------------
__global__ void pool_kv_kernel(const float* __restrict__ cwk, const float* __restrict__ ggk,
                               const float* __restrict__ bbk,
                               const float* __restrict__ cwv, const float* __restrict__ ggv,
                               const float* __restrict__ bbv)
{
    __shared__ float p1[3], p2[3], mv[2];
    int whichV = blockIdx.y;
    const float* cw = whichV ? cwv : cwk;
    const float* gg = whichV ? ggv : ggk;
    const float* bb = whichV ? bbv : bbk;
    int o    = blockIdx.x;
    int n    = o % KN;
    int head = (o / KN) & 1;
    int b    = o / (KN * 2);
    int c    = threadIdx.x;

    const float* src = whichV ? g_v : g_k;
    float* outp      = whichV ? g_vp : g_kp;

    float val;
    if (n == 0) {
        val = src[((size_t)b * NKV) * 192 + head * 96 + c];
    } else {
        int tn  = n - 1;
        int t2  = tn / (KH * KW);
        int rem = tn % (KH * KW);
        int h2  = rem / KW, w2 = rem % KW;
        float s = 0.f;
        #pragma unroll
        for (int dt = 0; dt < 3; ++dt) {
            int it = t2 + dt - 1;
            if (it < 0 || it >= T_IN) continue;
            #pragma unroll
            for (int dh = 0; dh < 3; ++dh) {
                int ih = h2 * 8 + dh - 1;
                if (ih < 0 || ih >= H_IN) continue;
                #pragma unroll
                for (int dw = 0; dw < 3; ++dw) {
                    int iw = w2 * 8 + dw - 1;
                    if (iw < 0 || iw >= W_IN) continue;
                    int ci = 1 + (it * 20 + idx_from_hw(ih)) * 20 + idx_from_hw(iw);
                    s = fmaf(cw[c * 27 + (dt * 3 + dh) * 3 + dw],
                             src[((size_t)(b * NKV + ci)) * 192 + head * 96 + c], s);
                }
            }
        }
        val = s;
    }
    float outv = ln96(val, gg, bb, c, p1, p2, mv);
    outp[((size_t)((b * 2 + head) * KN) + n) * 96 + c] = outv;
}

// ============================================================================
// FA2-style attention: 128 q-rows/block, 8 warps x 16 rows, register P
// ============================================================================
#define ASM_KH   0
#define ASM_KL   13312
#define ASM_VH   26624
#define ASM_VL   39936
#define ASM_SREL 53248
#define ASM_JMAP 65536
#define ATTN_SMEM2 67328

__global__ void __launch_bounds__(256) attn_fa2_kernel(
    const float* __restrict__ rph, const float* __restrict__ rpw,
    const float* __restrict__ rpt)
{
    extern __shared__ char sm[];
    float* Qf = (float*)sm;   // [128][98] fp32, phase 1 only (overlaid by K/V)
    __nv_bfloat16* Kh = (__nv_bfloat16*)(sm + ASM_KH);
    __nv_bfloat16* Kl = (__nv_bfloat16*)(sm + ASM_KL);
    __nv_bfloat16* Vh = (__nv_bfloat16*)(sm + ASM_VH);
    __nv_bfloat16* Vl = (__nv_bfloat16*)(sm + ASM_VL);
    float* srel = (float*)(sm + ASM_SREL);   // [128][24]
    u32* jmap = (u32*)(sm + ASM_JMAP);       // [448]
    u32 smb = smem_u32(sm);

    int tid = threadIdx.x;
    int warp = tid >> 5, lane = tid & 31;
    int gr = lane >> 2;
    int wr0 = warp * 16;
    int bh = blockIdx.y;
    int q0 = blockIdx.x * 128;
    const float* qp = g_qp + (size_t)bh * QN * 96;
    const float* kp = g_kp + (size_t)bh * KN * 96;
    const float* vp = g_vp + (size_t)bh * KN * 96;

    // ---- phase 1: stage Q fp32, build jmap ----
    for (int l = tid; l < 128 * 48; l += 256) {
        int row = l / 48, col = (l - row * 48) * 2;
        int qr = q0 + row;
        float2 v = (qr < QN) ? *(const float2*)&qp[(size_t)qr * 96 + col]
                             : make_float2(0.f, 0.f);
        *(float2*)&Qf[row * 98 + col] = v;
    }
    for (int j = tid; j < 448; j += 256) {
        u32 m = 0xFFFFFFFFu;
        if (j > 0 && j < KN) {
            int kk = j - 1, kt = kk / 49, rm = kk % 49;
            m = (u32)kt | ((u32)(rm / 7) << 8) | ((u32)(rm % 7) << 16);
        }
        jmap[j] = m;
    }
    __syncthreads();

    // ---- rel-pos dots ----
    for (int idx = tid; idx < 128 * 22; idx += 256) {
        int qi = idx / 22, r = idx - qi * 22;
        int qr = q0 + qi;
        float s = 0.f;
        if (qr > 0 && qr < QN) {
            int tok = qr - 1;
            int tq = tok / (QH * QW);
            int hq = (tok / QW) % QH;
            int wq = tok % QW;
            const float* tab;
            if (r < 8)       tab = rpt + (size_t)(tq - r + 7) * 96;
            else if (r < 15) tab = rph + (size_t)(hq - 4 * (r - 8) + 24) * 96;
            else             tab = rpw + (size_t)(wq - 4 * (r - 15) + 24) * 96;
            #pragma unroll 4
            for (int k = 0; k < 96; ++k) s = fmaf(Qf[qi * 98 + k], tab[k], s);
        }
        srel[qi * 24 + r] = s;
    }

    // ---- Q a-fragments (hi/lo), loaded once ----
    u32 qh[6][4], ql[6][4];
    {
        int rA = wr0 + gr;
        int c2 = 2 * (lane & 3);
        #pragma unroll
        for (int ks = 0; ks < 6; ++ks) {
            int kb = ks * 16;
            float2 v0 = *(const float2*)&Qf[rA * 98 + kb + c2];
            float2 v1 = *(const float2*)&Qf[(rA + 8) * 98 + kb + c2];
            float2 v2 = *(const float2*)&Qf[rA * 98 + kb + 8 + c2];
            float2 v3 = *(const float2*)&Qf[(rA + 8) * 98 + kb + 8 + c2];
            qh[ks][0] = pack_hi(v0.x, v0.y, ql[ks][0]);
            qh[ks][1] = pack_hi(v1.x, v1.y, ql[ks][1]);
            qh[ks][2] = pack_hi(v2.x, v2.y, ql[ks][2]);
            qh[ks][3] = pack_hi(v3.x, v3.y, ql[ks][3]);
        }
    }

    int qrA = q0 + wr0 + gr;
    int qrB = qrA + 8;
    bool relA = (qrA > 0 && qrA < QN);
    bool relB = (qrB > 0 && qrB < QN);
    const float* srelA = srel + (wr0 + gr) * 24;
    const float* srelB = srelA + 8 * 24;

    float O[12][4];
    #pragma unroll
    for (int nt = 0; nt < 12; ++nt)
        #pragma unroll
        for (int i = 0; i < 4; ++i) O[nt][i] = 0.f;
    float sumA = 0.f, sumB = 0.f;

    for (int ch = 0; ch < 7; ++ch) {
        int j0 = ch * 64;
        __syncthreads();     // Qf reads (first iter) / prev chunk compute done
        // stage K and V chunks (hi/lo split), stride 104
        for (int l = tid; l < 64 * 48; l += 256) {
            int jc = l / 48, col = (l - jc * 48) * 2;
            int j = j0 + jc;
            float2 kvv = (j < KN) ? *(const float2*)&kp[(size_t)j * 96 + col]
                                  : make_float2(0.f, 0.f);
            split_store(Kh, Kl, jc * 104 + col, kvv);
            float2 vvv = (j < KN) ? *(const float2*)&vp[(size_t)j * 96 + col]
                                  : make_float2(0.f, 0.f);
            split_store(Vh, Vl, jc * 104 + col, vvv);
        }
        __syncthreads();

        // ---- QK^T -> S (16 x 64 per warp) ----
        float S[8][4];
        #pragma unroll
        for (int jt = 0; jt < 8; ++jt)
            #pragma unroll
            for (int i = 0; i < 4; ++i) S[jt][i] = 0.f;

        #pragma unroll
        for (int ks = 0; ks < 6; ++ks) {
            #pragma unroll
            for (int jt2 = 0; jt2 < 4; ++jt2) {
                u32 addr = smb + ASM_KH
                         + (u32)(jt2 * 16 + ((lane >> 4) << 3) + (lane & 7)) * 208u
                         + (u32)(ks * 16 + ((lane >> 3) & 1) * 8) * 2u;
                u32 bh4[4], bl4[4];
                ldm_x4(bh4, addr);
                ldm_x4(bl4, addr + (ASM_KL - ASM_KH));
                mma_bf16(S[2 * jt2],     qh[ks], bh4);
                mma_bf16(S[2 * jt2],     qh[ks], bl4);
                mma_bf16(S[2 * jt2],     ql[ks], bh4);
                mma_bf16(S[2 * jt2 + 1], qh[ks], bh4 + 2);
                mma_bf16(S[2 * jt2 + 1], qh[ks], bl4 + 2);
                mma_bf16(S[2 * jt2 + 1], ql[ks], bh4 + 2);
            }
        }

        // ---- exp + rel-pos in registers ----
        #pragma unroll
        for (int jt = 0; jt < 8; ++jt) {
            #pragma unroll
            for (int e = 0; e < 4; ++e) {
                int j = j0 + jt * 8 + 2 * (lane & 3) + (e & 1);
                float ev = 0.f;
                if (j < KN) {
                    float s = S[jt][e] * ATTN_SCALE;
                    bool rr = (e < 2) ? relA : relB;
                    u32 m = jmap[j];
                    if (rr && m != 0xFFFFFFFFu) {
                        const float* sr = (e < 2) ? srelA : srelB;
                        s += sr[m & 0xFF] + sr[8 + ((m >> 8) & 0xFF)]
                           + sr[15 + ((m >> 16) & 0xFF)];
                    }
                    ev = __expf(s);
                    if (e < 2) sumA += ev; else sumB += ev;
                }
                S[jt][e] = ev;
            }
        }

        // ---- repack S as P a-fragments (hi/lo) ----
        u32 ph[4][4], pl[4][4];
        #pragma unroll
        for (int t = 0; t < 4; ++t) {
            ph[t][0] = pack_hi(S[2 * t][0],     S[2 * t][1],     pl[t][0]);
            ph[t][1] = pack_hi(S[2 * t][2],     S[2 * t][3],     pl[t][1]);
            ph[t][2] = pack_hi(S[2 * t + 1][0], S[2 * t + 1][1], pl[t][2]);
            ph[t][3] = pack_hi(S[2 * t + 1][2], S[2 * t + 1][3], pl[t][3]);
        }

        // ---- P @ V ----
        #pragma unroll
        for (int kt = 0; kt < 4; ++kt) {
            #pragma unroll
            for (int nt2 = 0; nt2 < 6; ++nt2) {
                u32 addr = smb + ASM_VH
                         + (u32)(kt * 16 + ((lane >> 3) & 1) * 8 + (lane & 7)) * 208u
                         + (u32)(nt2 * 16 + ((lane >> 4) << 3)) * 2u;
                u32 vh4[4], vl4[4];
                ldm_x4t(vh4, addr);
                ldm_x4t(vl4, addr + (ASM_VL - ASM_VH));
                mma_bf16(O[2 * nt2],     ph[kt], vh4);
                mma_bf16(O[2 * nt2],     ph[kt], vl4);
                mma_bf16(O[2 * nt2],     pl[kt], vh4);
                mma_bf16(O[2 * nt2 + 1], ph[kt], vh4 + 2);
                mma_bf16(O[2 * nt2 + 1], ph[kt], vl4 + 2);
                mma_bf16(O[2 * nt2 + 1], pl[kt], vh4 + 2);
            }
        }
    }

    // ---- row sums: reduce over the 4 quad lanes ----
    sumA += __shfl_xor_sync(0xffffffffu, sumA, 1);
    sumA += __shfl_xor_sync(0xffffffffu, sumA, 2);
    sumB += __shfl_xor_sync(0xffffffffu, sumB, 1);
    sumB += __shfl_xor_sync(0xffffffffu, sumB, 2);
    float riA = 1.f / sumA;
    float riB = 1.f / sumB;

    // ---- epilogue: normalize + residual + store ----
    int b = bh >> 1, head = bh & 1;
    int c2 = 2 * (lane & 3);
    if (qrA < QN) {
        #pragma unroll
        for (int nt = 0; nt < 12; ++nt) {
            int col = nt * 8 + c2;
            float2 qv = *(const float2*)&qp[(size_t)qrA * 96 + col];
            float2 o = make_float2(O[nt][0] * riA + qv.x, O[nt][1] * riA + qv.y);
            *(float2*)&g_ao[((size_t)(b * QN + qrA)) * 192 + head * 96 + col] = o;
        }
    }
    if (qrB < QN) {
        #pragma unroll
        for (int nt = 0; nt < 12; ++nt) {
            int col = nt * 8 + c2;
            float2 qv = *(const float2*)&qp[(size_t)qrB * 96 + col];
            float2 o = make_float2(O[nt][2] * riB + qv.x, O[nt][3] * riB + qv.y);
            *(float2*)&g_ao[((size_t)(b * QN + qrB)) * 192 + head * 96 + col] = o;
        }
    }
}

// ---------------- launch ----------------
extern "C" void kernel_launch(void* const* d_in, const int* in_sizes, int n_in,
                              void* d_out, int out_size)
{
    const float* x      = (const float*)d_in[0];
    const float* qkv_w  = (const float*)d_in[1];
    const float* qkv_b  = (const float*)d_in[2];
    const float* proj_w = (const float*)d_in[3];
    const float* proj_b = (const float*)d_in[4];
    const float* pq_w   = (const float*)d_in[5];
    const float* nq_g   = (const float*)d_in[6];
    const float* nq_b   = (const float*)d_in[7];
    const float* pk_w   = (const float*)d_in[8];
    const float* nk_g   = (const float*)d_in[9];
    const float* nk_b   = (const float*)d_in[10];
    const float* pv_w   = (const float*)d_in[11];
    const float* nv_g   = (const float*)d_in[12];
    const float* nv_b   = (const float*)d_in[13];
    const float* rph    = (const float*)d_in[14];
    const float* rpw    = (const float*)d_in[15];
    const float* rpt    = (const float*)d_in[16];

    int B = in_sizes[0] / (N_IN * 96);
    if (B > B_MAX) B = B_MAX;
    int M   = B * N_IN;
    int Mkv = B * NKV;

    cudaFuncSetAttribute(gemm192_mma, cudaFuncAttributeMaxDynamicSharedMemorySize, GEMM_SMEM);
    cudaFuncSetAttribute(attn_fa2_kernel, cudaFuncAttributeMaxDynamicSharedMemorySize, ATTN_SMEM2);

    gemm192_mma<<<(M + 127) / 128, 256, GEMM_SMEM>>>(x, qkv_w, qkv_b, nullptr, M, 96, 0);
    gemm192_mma<<<dim3((Mkv + 127) / 128, 2), 256, GEMM_SMEM>>>(x, qkv_w, qkv_b,
                                                                nullptr, Mkv, 96, 2);
    int nSpatial = B * 2 * QH * QW;
    pool_q_kernel<<<nSpatial + B * 2, 96>>>(pq_w, nq_g, nq_b, nSpatial);
    pool_kv_kernel<<<dim3(B * 2 * KN, 2), 96>>>(pk_w, nk_g, nk_b, pv_w, nv_g, nv_b);
    attn_fa2_kernel<<<dim3((QN + 127) / 128, B * 2), 256, ATTN_SMEM2>>>(rph, rpw, rpt);
    gemm192_mma<<<(B * QN + 127) / 128, 256, GEMM_SMEM>>>(nullptr, proj_w, proj_b,
                                                          (float*)d_out, B * QN, 192, 1);
}

// round 9
// speedup vs baseline: 1.5634x; 1.0902x over previous
#include <cuda_runtime.h>
#include <cuda_bf16.h>
#include <math.h>

typedef unsigned long long u64;
typedef unsigned int u32;

#define B_MAX 4
#define N_IN 25089      // 1 + 8*56*56
#define T_IN 8
#define H_IN 56
#define W_IN 56
#define QT 8
#define QH 28
#define QW 28
#define QN 6273         // 1 + 8*28*28
#define KT 8
#define KH 7
#define KW 7
#define KN 393          // 1 + 8*7*7
#define NKV 3201        // 1 + 8*20*20 gathered tokens per batch
#define ATTN_SCALE 0.102062072615965745f   // 1/sqrt(96)

// ---------------- scratch (device globals; no allocation) ----------------
__device__ float g_q [(size_t)B_MAX * N_IN * 192];
__device__ float g_k [(size_t)B_MAX * NKV * 192];
__device__ float g_v [(size_t)B_MAX * NKV * 192];
__device__ float g_qp[(size_t)B_MAX * 2 * QN * 96];
__device__ float g_kp[(size_t)B_MAX * 2 * KN * 96];
__device__ float g_vp[(size_t)B_MAX * 2 * KN * 96];
// bf16 hi/lo pre-split inputs
__device__ __nv_bfloat16 g_xh[(size_t)B_MAX * N_IN * 96];
__device__ __nv_bfloat16 g_xl[(size_t)B_MAX * N_IN * 96];
__device__ __nv_bfloat16 g_wh[576 * 96];
__device__ __nv_bfloat16 g_wl[576 * 96];
__device__ __nv_bfloat16 g_pwh[192 * 192];
__device__ __nv_bfloat16 g_pwl[192 * 192];
__device__ __nv_bfloat16 g_aoh[(size_t)B_MAX * QN * 192];
__device__ __nv_bfloat16 g_aol[(size_t)B_MAX * QN * 192];

// ---------------- helpers ----------------
__device__ __forceinline__ int hw_from_idx(int i) {
    return (i < 2) ? i : 7 + ((i - 2) / 3) * 8 + ((i - 2) % 3);
}
__device__ __forceinline__ int idx_from_hw(int v) {
    return (v <= 1) ? v : 2 + ((v - 7) >> 3) * 3 + ((v - 7) & 7);
}
__device__ __forceinline__ u32 smem_u32(const void* p) {
    u32 a;
    asm("{ .reg .u64 t; cvta.to.shared.u64 t, %1; cvt.u32.u64 %0, t; }" : "=r"(a) : "l"(p));
    return a;
}

// ---------------- mma.sync helpers ----------------
__device__ __forceinline__ void ldm_x4(u32* r, u32 addr) {
    asm volatile("ldmatrix.sync.aligned.m8n8.x4.shared.b16 {%0,%1,%2,%3}, [%4];"
        : "=r"(r[0]), "=r"(r[1]), "=r"(r[2]), "=r"(r[3]) : "r"(addr));
}
__device__ __forceinline__ void ldm_x4t(u32* r, u32 addr) {
    asm volatile("ldmatrix.sync.aligned.m8n8.x4.trans.shared.b16 {%0,%1,%2,%3}, [%4];"
        : "=r"(r[0]), "=r"(r[1]), "=r"(r[2]), "=r"(r[3]) : "r"(addr));
}
__device__ __forceinline__ void mma_bf16(float* c, const u32* a, const u32* b) {
    asm volatile("mma.sync.aligned.m16n8k16.row.col.f32.bf16.bf16.f32 "
        "{%0,%1,%2,%3}, {%4,%5,%6,%7}, {%8,%9}, {%0,%1,%2,%3};"
        : "+f"(c[0]), "+f"(c[1]), "+f"(c[2]), "+f"(c[3])
        : "r"(a[0]), "r"(a[1]), "r"(a[2]), "r"(a[3]), "r"(b[0]), "r"(b[1]));
}
__device__ __forceinline__ void split_store(__nv_bfloat16* hi, __nv_bfloat16* lo,
                                            int idx, float2 v) {
    __nv_bfloat162 h = __floats2bfloat162_rn(v.x, v.y);
    __nv_bfloat162 l = __floats2bfloat162_rn(v.x - __bfloat162float(h.x),
                                             v.y - __bfloat162float(h.y));
    *(__nv_bfloat162*)(hi + idx) = h;
    *(__nv_bfloat162*)(lo + idx) = l;
}
__device__ __forceinline__ u32 pack_hi(float a, float b, u32& lo) {
    __nv_bfloat162 h = __floats2bfloat162_rn(a, b);
    __nv_bfloat162 l = __floats2bfloat162_rn(a - __bfloat162float(h.x),
                                             b - __bfloat162float(h.y));
    lo = *(u32*)&l;
    return *(u32*)&h;
}
__device__ __forceinline__ void cpa16(u32 dst, const void* src, int srcsize) {
    asm volatile("cp.async.cg.shared.global [%0], [%1], 16, %2;"
        :: "r"(dst), "l"(src), "r"(srcsize));
}
#define CP_COMMIT() asm volatile("cp.async.commit_group;" ::: "memory")

// ---------------- presplit: x / qkv_w / proj_w -> bf16 hi/lo ----------------
__global__ void presplit_kernel(const float* __restrict__ x,
                                const float* __restrict__ qkv_w,
                                const float* __restrict__ proj_w, int nx)
{
    int i = blockIdx.x * 256 + threadIdx.x;   // float2 pair index
    const int nqkv = 576 * 96 / 2;
    const int nproj = 192 * 192 / 2;
    const float* src;
    __nv_bfloat16 *dh, *dl;
    int off;
    if (i < nx)                   { src = x;      dh = g_xh;  dl = g_xl;  off = i; }
    else if (i < nx + nqkv)       { src = qkv_w;  dh = g_wh;  dl = g_wl;  off = i - nx; }
    else if (i < nx + nqkv + nproj) { src = proj_w; dh = g_pwh; dl = g_pwl; off = i - nx - nqkv; }
    else return;
    float2 v = ((const float2*)src)[off];
    split_store(dh, dl, 2 * off, v);
}

// ============================================================================
// cp.async double-buffered bf16 tensor-core GEMM, out[M,192] = A @ B^T + bias
// fused=1: grid = nbQ + 2*nbKV  (Q direct / K gather / V gather), K=96
// fused=0: proj, A = g_aoh/g_aol, B = g_pwh/g_pwl, K=192, out=outp
// ============================================================================
// per-stage smem: Ah[128][40] Al | Bh[192][40] Bl  (bf16, 80B row stride)
#define STG_BYTES 51200
#define STG_AL 10240
#define STG_B  20480
#define STG_BL 15360
#define GEMM_SMEM (2 * STG_BYTES)

__global__ void __launch_bounds__(256) gemm_bf16(
    const float* __restrict__ bias_all, float* __restrict__ outp,
    int Mq, int Mkv, int K, int nbQ, int nbKV, int fused)
{
    extern __shared__ char sm[];
    u32 smb = smem_u32(sm);

    int tid = threadIdx.x;
    int warp = tid >> 5, lane = tid & 31;
    int rm = (warp & 3) * 32;
    int cn = (warp >> 2) * 96;

    const __nv_bfloat16 *Asrc_h, *Asrc_l, *Bsrc_h, *Bsrc_l;
    const float* bp;
    float* out;
    int r0, Mloc;
    bool gather = false;
    if (!fused) {
        Asrc_h = g_aoh; Asrc_l = g_aol; Bsrc_h = g_pwh; Bsrc_l = g_pwl;
        bp = bias_all; out = outp; r0 = blockIdx.x * 128; Mloc = Mq;
    } else if ((int)blockIdx.x < nbQ) {
        Asrc_h = g_xh; Asrc_l = g_xl; Bsrc_h = g_wh; Bsrc_l = g_wl;
        bp = bias_all; out = (float*)g_q; r0 = blockIdx.x * 128; Mloc = Mq;
    } else {
        int t = blockIdx.x - nbQ;
        int sel = t / nbKV, bx2 = t - sel * nbKV;
        gather = true;
        Asrc_h = g_xh; Asrc_l = g_xl;
        Bsrc_h = g_wh + (size_t)(1 + sel) * 192 * 96;
        Bsrc_l = g_wl + (size_t)(1 + sel) * 192 * 96;
        bp = bias_all + (1 + sel) * 192;
        out = sel ? (float*)g_v : (float*)g_k;
        r0 = bx2 * 128; Mloc = Mkv;
    }

    // precompute per-thread A source row offsets (rows fixed across chunks)
    size_t aoff[4];
    int asz[4];
    #pragma unroll
    for (int k4 = 0; k4 < 4; ++k4) {
        int l = tid + k4 * 256;
        int row = l >> 3;
        int r = r0 + row;
        if (r < Mloc) {
            asz[k4] = 16;
            if (gather) {
                int b = r / NKV, ci = r - b * NKV;
                int n = 0;
                if (ci > 0) {
                    int cc = ci - 1;
                    int it = cc / 400, rem = cc - it * 400;
                    int h = hw_from_idx(rem / 20), wv = hw_from_idx(rem % 20);
                    n = 1 + (it * H_IN + h) * W_IN + wv;
                }
                aoff[k4] = ((size_t)b * N_IN + n) * 96;
            } else {
                aoff[k4] = (size_t)r * K;
            }
        } else { aoff[k4] = 0; asz[k4] = 0; }
    }

    float C[2][12][4];
    #pragma unroll
    for (int mt = 0; mt < 2; ++mt)
        #pragma unroll
        for (int nt = 0; nt < 12; ++nt)
            #pragma unroll
            for (int i = 0; i < 4; ++i) C[mt][nt][i] = 0.f;

    int nch = K / 32;

    // ---- issue helper (lambda-free, inline twice) ----
    // issue chunk c into stage st
    #define ISSUE_CHUNK(c_, st_) do {                                          \
        int kc = (c_) * 32;                                                    \
        u32 sb = smb + (st_) * STG_BYTES;                                      \
        _Pragma("unroll")                                                      \
        for (int k4 = 0; k4 < 4; ++k4) {                                       \
            int l = tid + k4 * 256;                                            \
            int row = l >> 3, hl = (l >> 2) & 1, seg = l & 3;                  \
            u32 dst = sb + hl * STG_AL + (u32)row * 80u + (u32)seg * 16u;      \
            const __nv_bfloat16* s0 = hl ? Asrc_l : Asrc_h;                    \
            cpa16(dst, s0 + aoff[k4] + kc + seg * 8, asz[k4]);                 \
        }                                                                      \
        _Pragma("unroll")                                                      \
        for (int k6 = 0; k6 < 6; ++k6) {                                       \
            int l = tid + k6 * 256;                                            \
            int row = l >> 3, hl = (l >> 2) & 1, seg = l & 3;                  \
            u32 dst = sb + STG_B + hl * STG_BL + (u32)row * 80u + (u32)seg * 16u; \
            const __nv_bfloat16* s0 = hl ? Bsrc_l : Bsrc_h;                    \
            cpa16(dst, s0 + (size_t)row * K + kc + seg * 8, 16);               \
        }                                                                      \
        CP_COMMIT();                                                           \
    } while (0)

    ISSUE_CHUNK(0, 0);

    for (int c = 0; c < nch; ++c) {
        int st = c & 1;
        if (c + 1 < nch) {
            ISSUE_CHUNK(c + 1, st ^ 1);
            asm volatile("cp.async.wait_group 1;" ::: "memory");
        } else {
            asm volatile("cp.async.wait_group 0;" ::: "memory");
        }
        __syncthreads();

        u32 sb = smb + st * STG_BYTES;
        #pragma unroll
        for (int ks = 0; ks < 2; ++ks) {
            int k0 = ks * 16;
            u32 ah[2][4], al[2][4];
            #pragma unroll
            for (int mt = 0; mt < 2; ++mt) {
                u32 off = (u32)(rm + mt * 16 + (lane & 15)) * 80u
                        + (u32)(k0 + ((lane >> 4) << 3)) * 2u;
                ldm_x4(ah[mt], sb + off);
                ldm_x4(al[mt], sb + STG_AL + off);
            }
            #pragma unroll
            for (int np = 0; np < 6; ++np) {
                u32 off = (u32)(cn + np * 16 + ((lane >> 4) << 3) + (lane & 7)) * 80u
                        + (u32)(k0 + (((lane >> 3) & 1) << 3)) * 2u;
                u32 bh4[4], bl4[4];
                ldm_x4(bh4, sb + STG_B + off);
                ldm_x4(bl4, sb + STG_B + STG_BL + off);
                #pragma unroll
                for (int mt = 0; mt < 2; ++mt) {
                    mma_bf16(C[mt][2 * np],     ah[mt], bh4);
                    mma_bf16(C[mt][2 * np],     ah[mt], bl4);
                    mma_bf16(C[mt][2 * np],     al[mt], bh4);
                    mma_bf16(C[mt][2 * np + 1], ah[mt], bh4 + 2);
                    mma_bf16(C[mt][2 * np + 1], ah[mt], bl4 + 2);
                    mma_bf16(C[mt][2 * np + 1], al[mt], bh4 + 2);
                }
            }
        }
        __syncthreads();
    }

    int gr = lane >> 2;
    int gc = (lane & 3) * 2;
    #pragma unroll
    for (int mt = 0; mt < 2; ++mt) {
        int row0 = r0 + rm + mt * 16 + gr;
        int row1 = row0 + 8;
        #pragma unroll
        for (int nt = 0; nt < 12; ++nt) {
            int col = cn + nt * 8 + gc;
            float b0 = bp[col], b1 = bp[col + 1];
            if (row0 < Mloc) {
                float2 o = make_float2(C[mt][nt][0] + b0, C[mt][nt][1] + b1);
                *(float2*)&out[(size_t)row0 * 192 + col] = o;
            }
            if (row1 < Mloc) {
                float2 o = make_float2(C[mt][nt][2] + b0, C[mt][nt][3] + b1);
                *(float2*)&out[(size_t)row1 * 192 + col] = o;
            }
        }
    }
}

// ---------------- LN helper (96 threads) ----------------
__device__ __forceinline__ float ln96(float val, const float* gg, const float* bb, int c,
                                      float* p1, float* p2, float* mv)
{
    float s1 = val, s2 = val * val;
    #pragma unroll
    for (int off = 16; off > 0; off >>= 1) {
        s1 += __shfl_xor_sync(0xffffffffu, s1, off);
        s2 += __shfl_xor_sync(0xffffffffu, s2, off);
    }
    int wid = c >> 5, lane = c & 31;
    if (lane == 0) { p1[wid] = s1; p2[wid] = s2; }
    __syncthreads();
    if (c == 0) {
        float t1 = p1[0] + p1[1] + p1[2];
        float t2 = p2[0] + p2[1] + p2[2];
        float mean = t1 / 96.f;
        float var  = t2 / 96.f - mean * mean;
        mv[0] = mean; mv[1] = rsqrtf(var + 1e-5f);
    }
    __syncthreads();
    return (val - mv[0]) * mv[1] * gg[c] + bb[c];
}

// ---------------- Q pool: register plane-sums; cls folded in ----------------
__global__ void pool_q_kernel(const float* __restrict__ cw, const float* __restrict__ gg,
                              const float* __restrict__ bb, int nSpatial)
{
    __shared__ float p1[3], p2[3], mv[2];
    int o = blockIdx.x;
    int c = threadIdx.x;

    if (o >= nSpatial) {
        int idx = o - nSpatial;
        int head = idx & 1, b = idx >> 1;
        float val = g_q[((size_t)b * N_IN) * 192 + head * 96 + c];
        float outv = ln96(val, gg, bb, c, p1, p2, mv);
        g_qp[((size_t)((b * 2 + head) * QN)) * 96 + c] = outv;
        return;
    }

    int w2 = o % QW;
    int h2 = (o / QW) % QH;
    int head = (o / (QW * QH)) & 1;
    int b = o / (QW * QH * 2);

    float wreg[27];
    #pragma unroll
    for (int t = 0; t < 27; ++t) wreg[t] = cw[c * 27 + t];

    float ps[8][3];
    #pragma unroll
    for (int it = 0; it < 8; ++it)
        #pragma unroll
        for (int d = 0; d < 3; ++d) ps[it][d] = 0.f;

    const float* base = g_q + ((size_t)(b * N_IN + 1)) * 192 + head * 96 + c;
    #pragma unroll
    for (int dh = 0; dh < 3; ++dh) {
        int ih = 2 * h2 - 1 + dh;
        if (ih < 0 || ih >= H_IN) continue;
        #pragma unroll
        for (int dw = 0; dw < 3; ++dw) {
            int iw = 2 * w2 - 1 + dw;
            if (iw < 0 || iw >= W_IN) continue;
            float w0 = wreg[(0 * 3 + dh) * 3 + dw];
            float w1 = wreg[(1 * 3 + dh) * 3 + dw];
            float w2r = wreg[(2 * 3 + dh) * 3 + dw];
            #pragma unroll
            for (int it = 0; it < 8; ++it) {
                int tok = (it * H_IN + ih) * W_IN + iw;
                float v = base[(size_t)tok * 192];
                ps[it][0] = fmaf(w0, v, ps[it][0]);
                ps[it][1] = fmaf(w1, v, ps[it][1]);
                ps[it][2] = fmaf(w2r, v, ps[it][2]);
            }
        }
    }

    for (int t2 = 0; t2 < QT; ++t2) {
        float s = ps[t2][1];
        if (t2 > 0) s += ps[t2 - 1][0];
        if (t2 < 7) s += ps[t2 + 1][2];
        float outv = ln96(s, gg, bb, c, p1, p2, mv);
        int n = 1 + (t2 * QH + h2) * QW + w2;
        g_qp[((size_t)((b * 2 + head) * QN) + n) * 96 + c] = outv;
        __syncthreads();
    }
}

// ---------------- K/V pool + LN, merged via blockIdx.y ----------------
__global__ void pool_kv_kernel(const float* __restrict__ cwk, const float* __restrict__ ggk,
                               const float* __restrict__ bbk,
                               const float* __restrict__ cwv, const float* __restrict__ ggv,
                               const float* __restrict__ bbv)
{
    __shared__ float p1[3], p2[3], mv[2];
    int whichV = blockIdx.y;
    const float* cw = whichV ? cwv : cwk;
    const float* gg = whichV ? ggv : ggk;
    const float* bb = whichV ? bbv : bbk;
    int o    = blockIdx.x;
    int n    = o % KN;
    int head = (o / KN) & 1;
    int b    = o / (KN * 2);
    int c    = threadIdx.x;

    const float* src = whichV ? g_v : g_k;
    float* outp      = whichV ? g_vp : g_kp;

    float val;
    if (n == 0) {
        val = src[((size_t)b * NKV) * 192 + head * 96 + c];
    } else {
        int tn  = n - 1;
        int t2  = tn / (KH * KW);
        int rem = tn % (KH * KW);
        int h2  = rem / KW, w2 = rem % KW;
        float s = 0.f;
        #pragma unroll
        for (int dt = 0; dt < 3; ++dt) {
            int it = t2 + dt - 1;
            if (it < 0 || it >= T_IN) continue;
            #pragma unroll
            for (int dh = 0; dh < 3; ++dh) {
                int ih = h2 * 8 + dh - 1;
                if (ih < 0 || ih >= H_IN) continue;
                #pragma unroll
                for (int dw = 0; dw < 3; ++dw) {
                    int iw = w2 * 8 + dw - 1;
                    if (iw < 0 || iw >= W_IN) continue;
                    int ci = 1 + (it * 20 + idx_from_hw(ih)) * 20 + idx_from_hw(iw);
                    s = fmaf(cw[c * 27 + (dt * 3 + dh) * 3 + dw],
                             src[((size_t)(b * NKV + ci)) * 192 + head * 96 + c], s);
                }
            }
        }
        val = s;
    }
    float outv = ln96(val, gg, bb, c, p1, p2, mv);
    outp[((size_t)((b * 2 + head) * KN) + n) * 96 + c] = outv;
}

// ============================================================================
// FA2-style attention: 128 q-rows/block, 8 warps x 16 rows, register P
// ============================================================================
#define ASM_KH   0
#define ASM_KL   13312
#define ASM_VH   26624
#define ASM_VL   39936
#define ASM_SREL 53248
#define ASM_JMAP 65536
#define ATTN_SMEM2 67328

__global__ void __launch_bounds__(256) attn_fa2_kernel(
    const float* __restrict__ rph, const float* __restrict__ rpw,
    const float* __restrict__ rpt)
{
    extern __shared__ char sm[];
    float* Qf = (float*)sm;   // [128][98] fp32, phase 1 only (overlaid by K/V)
    __nv_bfloat16* Kh = (__nv_bfloat16*)(sm + ASM_KH);
    __nv_bfloat16* Kl = (__nv_bfloat16*)(sm + ASM_KL);
    __nv_bfloat16* Vh = (__nv_bfloat16*)(sm + ASM_VH);
    __nv_bfloat16* Vl = (__nv_bfloat16*)(sm + ASM_VL);
    float* srel = (float*)(sm + ASM_SREL);   // [128][24]
    u32* jmap = (u32*)(sm + ASM_JMAP);       // [448]
    u32 smb = smem_u32(sm);

    int tid = threadIdx.x;
    int warp = tid >> 5, lane = tid & 31;
    int gr = lane >> 2;
    int wr0 = warp * 16;
    int bh = blockIdx.y;
    int q0 = blockIdx.x * 128;
    const float* qp = g_qp + (size_t)bh * QN * 96;
    const float* kp = g_kp + (size_t)bh * KN * 96;
    const float* vp = g_vp + (size_t)bh * KN * 96;

    // ---- phase 1: stage Q fp32, build jmap ----
    for (int l = tid; l < 128 * 48; l += 256) {
        int row = l / 48, col = (l - row * 48) * 2;
        int qr = q0 + row;
        float2 v = (qr < QN) ? *(const float2*)&qp[(size_t)qr * 96 + col]
                             : make_float2(0.f, 0.f);
        *(float2*)&Qf[row * 98 + col] = v;
    }
    for (int j = tid; j < 448; j += 256) {
        u32 m = 0xFFFFFFFFu;
        if (j > 0 && j < KN) {
            int kk = j - 1, kt = kk / 49, rm = kk % 49;
            m = (u32)kt | ((u32)(rm / 7) << 8) | ((u32)(rm % 7) << 16);
        }
        jmap[j] = m;
    }
    __syncthreads();

    // ---- rel-pos dots ----
    for (int idx = tid; idx < 128 * 22; idx += 256) {
        int qi = idx / 22, r = idx - qi * 22;
        int qr = q0 + qi;
        float s = 0.f;
        if (qr > 0 && qr < QN) {
            int tok = qr - 1;
            int tq = tok / (QH * QW);
            int hq = (tok / QW) % QH;
            int wq = tok % QW;
            const float* tab;
            if (r < 8)       tab = rpt + (size_t)(tq - r + 7) * 96;
            else if (r < 15) tab = rph + (size_t)(hq - 4 * (r - 8) + 24) * 96;
            else             tab = rpw + (size_t)(wq - 4 * (r - 15) + 24) * 96;
            #pragma unroll 4
            for (int k = 0; k < 96; ++k) s = fmaf(Qf[qi * 98 + k], tab[k], s);
        }
        srel[qi * 24 + r] = s;
    }

    // ---- Q a-fragments (hi/lo), loaded once ----
    u32 qh[6][4], ql[6][4];
    {
        int rA = wr0 + gr;
        int c2 = 2 * (lane & 3);
        #pragma unroll
        for (int ks = 0; ks < 6; ++ks) {
            int kb = ks * 16;
            float2 v0 = *(const float2*)&Qf[rA * 98 + kb + c2];
            float2 v1 = *(const float2*)&Qf[(rA + 8) * 98 + kb + c2];
            float2 v2 = *(const float2*)&Qf[rA * 98 + kb + 8 + c2];
            float2 v3 = *(const float2*)&Qf[(rA + 8) * 98 + kb + 8 + c2];
            qh[ks][0] = pack_hi(v0.x, v0.y, ql[ks][0]);
            qh[ks][1] = pack_hi(v1.x, v1.y, ql[ks][1]);
            qh[ks][2] = pack_hi(v2.x, v2.y, ql[ks][2]);
            qh[ks][3] = pack_hi(v3.x, v3.y, ql[ks][3]);
        }
    }

    int qrA = q0 + wr0 + gr;
    int qrB = qrA + 8;
    bool relA = (qrA > 0 && qrA < QN);
    bool relB = (qrB > 0 && qrB < QN);
    const float* srelA = srel + (wr0 + gr) * 24;
    const float* srelB = srelA + 8 * 24;

    float O[12][4];
    #pragma unroll
    for (int nt = 0; nt < 12; ++nt)
        #pragma unroll
        for (int i = 0; i < 4; ++i) O[nt][i] = 0.f;
    float sumA = 0.f, sumB = 0.f;

    for (int ch = 0; ch < 7; ++ch) {
        int j0 = ch * 64;
        __syncthreads();
        for (int l = tid; l < 64 * 48; l += 256) {
            int jc = l / 48, col = (l - jc * 48) * 2;
            int j = j0 + jc;
            float2 kvv = (j < KN) ? *(const float2*)&kp[(size_t)j * 96 + col]
                                  : make_float2(0.f, 0.f);
            split_store(Kh, Kl, jc * 104 + col, kvv);
            float2 vvv = (j < KN) ? *(const float2*)&vp[(size_t)j * 96 + col]
                                  : make_float2(0.f, 0.f);
            split_store(Vh, Vl, jc * 104 + col, vvv);
        }
        __syncthreads();

        // ---- QK^T -> S (16 x 64 per warp) ----
        float S[8][4];
        #pragma unroll
        for (int jt = 0; jt < 8; ++jt)
            #pragma unroll
            for (int i = 0; i < 4; ++i) S[jt][i] = 0.f;

        #pragma unroll
        for (int ks = 0; ks < 6; ++ks) {
            #pragma unroll
            for (int jt2 = 0; jt2 < 4; ++jt2) {
                u32 addr = smb + ASM_KH
                         + (u32)(jt2 * 16 + ((lane >> 4) << 3) + (lane & 7)) * 208u
                         + (u32)(ks * 16 + ((lane >> 3) & 1) * 8) * 2u;
                u32 bh4[4], bl4[4];
                ldm_x4(bh4, addr);
                ldm_x4(bl4, addr + (ASM_KL - ASM_KH));
                mma_bf16(S[2 * jt2],     qh[ks], bh4);
                mma_bf16(S[2 * jt2],     qh[ks], bl4);
                mma_bf16(S[2 * jt2],     ql[ks], bh4);
                mma_bf16(S[2 * jt2 + 1], qh[ks], bh4 + 2);
                mma_bf16(S[2 * jt2 + 1], qh[ks], bl4 + 2);
                mma_bf16(S[2 * jt2 + 1], ql[ks], bh4 + 2);
            }
        }

        // ---- exp + rel-pos in registers ----
        #pragma unroll
        for (int jt = 0; jt < 8; ++jt) {
            #pragma unroll
            for (int e = 0; e < 4; ++e) {
                int j = j0 + jt * 8 + 2 * (lane & 3) + (e & 1);
                float ev = 0.f;
                if (j < KN) {
                    float s = S[jt][e] * ATTN_SCALE;
                    bool rr = (e < 2) ? relA : relB;
                    u32 m = jmap[j];
                    if (rr && m != 0xFFFFFFFFu) {
                        const float* sr = (e < 2) ? srelA : srelB;
                        s += sr[m & 0xFF] + sr[8 + ((m >> 8) & 0xFF)]
                           + sr[15 + ((m >> 16) & 0xFF)];
                    }
                    ev = __expf(s);
                    if (e < 2) sumA += ev; else sumB += ev;
                }
                S[jt][e] = ev;
            }
        }

        // ---- repack S as P a-fragments (hi/lo) ----
        u32 ph[4][4], pl[4][4];
        #pragma unroll
        for (int t = 0; t < 4; ++t) {
            ph[t][0] = pack_hi(S[2 * t][0],     S[2 * t][1],     pl[t][0]);
            ph[t][1] = pack_hi(S[2 * t][2],     S[2 * t][3],     pl[t][1]);
            ph[t][2] = pack_hi(S[2 * t + 1][0], S[2 * t + 1][1], pl[t][2]);
            ph[t][3] = pack_hi(S[2 * t + 1][2], S[2 * t + 1][3], pl[t][3]);
        }

        // ---- P @ V ----
        #pragma unroll
        for (int kt = 0; kt < 4; ++kt) {
            #pragma unroll
            for (int nt2 = 0; nt2 < 6; ++nt2) {
                u32 addr = smb + ASM_VH
                         + (u32)(kt * 16 + ((lane >> 3) & 1) * 8 + (lane & 7)) * 208u
                         + (u32)(nt2 * 16 + ((lane >> 4) << 3)) * 2u;
                u32 vh4[4], vl4[4];
                ldm_x4t(vh4, addr);
                ldm_x4t(vl4, addr + (ASM_VL - ASM_VH));
                mma_bf16(O[2 * nt2],     ph[kt], vh4);
                mma_bf16(O[2 * nt2],     ph[kt], vl4);
                mma_bf16(O[2 * nt2],     pl[kt], vh4);
                mma_bf16(O[2 * nt2 + 1], ph[kt], vh4 + 2);
                mma_bf16(O[2 * nt2 + 1], ph[kt], vl4 + 2);
                mma_bf16(O[2 * nt2 + 1], pl[kt], vh4 + 2);
            }
        }
    }

    // ---- row sums: reduce over the 4 quad lanes ----
    sumA += __shfl_xor_sync(0xffffffffu, sumA, 1);
    sumA += __shfl_xor_sync(0xffffffffu, sumA, 2);
    sumB += __shfl_xor_sync(0xffffffffu, sumB, 1);
    sumB += __shfl_xor_sync(0xffffffffu, sumB, 2);
    float riA = 1.f / sumA;
    float riB = 1.f / sumB;

    // ---- epilogue: normalize + residual + store as bf16 hi/lo ----
    int b = bh >> 1, head = bh & 1;
    int c2 = 2 * (lane & 3);
    if (qrA < QN) {
        #pragma unroll
        for (int nt = 0; nt < 12; ++nt) {
            int col = nt * 8 + c2;
            float2 qv = *(const float2*)&qp[(size_t)qrA * 96 + col];
            float2 o = make_float2(O[nt][0] * riA + qv.x, O[nt][1] * riA + qv.y);
            split_store(g_aoh, g_aol,
                        (int)(((size_t)(b * QN + qrA)) * 192) + head * 96 + col, o);
        }
    }
    if (qrB < QN) {
        #pragma unroll
        for (int nt = 0; nt < 12; ++nt) {
            int col = nt * 8 + c2;
            float2 qv = *(const float2*)&qp[(size_t)qrB * 96 + col];
            float2 o = make_float2(O[nt][2] * riB + qv.x, O[nt][3] * riB + qv.y);
            split_store(g_aoh, g_aol,
                        (int)(((size_t)(b * QN + qrB)) * 192) + head * 96 + col, o);
        }
    }
}

// ---------------- launch ----------------
extern "C" void kernel_launch(void* const* d_in, const int* in_sizes, int n_in,
                              void* d_out, int out_size)
{
    const float* x      = (const float*)d_in[0];
    const float* qkv_w  = (const float*)d_in[1];
    const float* qkv_b  = (const float*)d_in[2];
    const float* proj_w = (const float*)d_in[3];
    const float* proj_b = (const float*)d_in[4];
    const float* pq_w   = (const float*)d_in[5];
    const float* nq_g   = (const float*)d_in[6];
    const float* nq_b   = (const float*)d_in[7];
    const float* pk_w   = (const float*)d_in[8];
    const float* nk_g   = (const float*)d_in[9];
    const float* nk_b   = (const float*)d_in[10];
    const float* pv_w   = (const float*)d_in[11];
    const float* nv_g   = (const float*)d_in[12];
    const float* nv_b   = (const float*)d_in[13];
    const float* rph    = (const float*)d_in[14];
    const float* rpw    = (const float*)d_in[15];
    const float* rpt    = (const float*)d_in[16];

    int B = in_sizes[0] / (N_IN * 96);
    if (B > B_MAX) B = B_MAX;
    int M   = B * N_IN;
    int Mkv = B * NKV;
    int nbQ  = (M + 127) / 128;
    int nbKV = (Mkv + 127) / 128;

    cudaFuncSetAttribute(gemm_bf16, cudaFuncAttributeMaxDynamicSharedMemorySize, GEMM_SMEM);
    cudaFuncSetAttribute(attn_fa2_kernel, cudaFuncAttributeMaxDynamicSharedMemorySize, ATTN_SMEM2);

    int nx = M * 48;   // float2 pairs in x
    int totalPairs = nx + 576 * 96 / 2 + 192 * 192 / 2;
    presplit_kernel<<<(totalPairs + 255) / 256, 256>>>(x, qkv_w, proj_w, nx);

    gemm_bf16<<<nbQ + 2 * nbKV, 256, GEMM_SMEM>>>(qkv_b, nullptr, M, Mkv, 96, nbQ, nbKV, 1);

    int nSpatial = B * 2 * QH * QW;
    pool_q_kernel<<<nSpatial + B * 2, 96>>>(pq_w, nq_g, nq_b, nSpatial);
    pool_kv_kernel<<<dim3(B * 2 * KN, 2), 96>>>(pk_w, nk_g, nk_b, pv_w, nv_g, nv_b);
    attn_fa2_kernel<<<dim3((QN + 127) / 128, B * 2), 256, ATTN_SMEM2>>>(rph, rpw, rpt);

    gemm_bf16<<<(B * QN + 127) / 128, 256, GEMM_SMEM>>>(proj_b, (float*)d_out,
                                                        B * QN, 0, 192, 0, 0, 0);
}

// round 10
// speedup vs baseline: 1.6749x; 1.0713x over previous
#include <cuda_runtime.h>
#include <cuda_bf16.h>
#include <math.h>

typedef unsigned long long u64;
typedef unsigned int u32;

#define B_MAX 4
#define N_IN 25089      // 1 + 8*56*56
#define T_IN 8
#define H_IN 56
#define W_IN 56
#define QT 8
#define QH 28
#define QW 28
#define QN 6273         // 1 + 8*28*28
#define KT 8
#define KH 7
#define KW 7
#define KN 393          // 1 + 8*7*7
#define NKV 3201        // 1 + 8*20*20 gathered tokens per batch
#define ATTN_SCALE 0.102062072615965745f   // 1/sqrt(96)

// ---------------- scratch (device globals; no allocation) ----------------
__device__ float g_q [(size_t)B_MAX * N_IN * 192];
__device__ float g_k [(size_t)B_MAX * NKV * 192];
__device__ float g_v [(size_t)B_MAX * NKV * 192];
__device__ float g_qp[(size_t)B_MAX * 2 * QN * 96];
// bf16 hi/lo pre-split tensors
__device__ __nv_bfloat16 g_xh[(size_t)B_MAX * N_IN * 96];
__device__ __nv_bfloat16 g_xl[(size_t)B_MAX * N_IN * 96];
__device__ __nv_bfloat16 g_wh[576 * 96];
__device__ __nv_bfloat16 g_wl[576 * 96];
__device__ __nv_bfloat16 g_pwh[192 * 192];
__device__ __nv_bfloat16 g_pwl[192 * 192];
__device__ __nv_bfloat16 g_aoh[(size_t)B_MAX * QN * 192];
__device__ __nv_bfloat16 g_aol[(size_t)B_MAX * QN * 192];
// pooled K/V pre-split
__device__ __nv_bfloat16 g_kph[(size_t)B_MAX * 2 * KN * 96];
__device__ __nv_bfloat16 g_kpl[(size_t)B_MAX * 2 * KN * 96];
__device__ __nv_bfloat16 g_vph[(size_t)B_MAX * 2 * KN * 96];
__device__ __nv_bfloat16 g_vpl[(size_t)B_MAX * 2 * KN * 96];

// ---------------- helpers ----------------
__device__ __forceinline__ int hw_from_idx(int i) {
    return (i < 2) ? i : 7 + ((i - 2) / 3) * 8 + ((i - 2) % 3);
}
__device__ __forceinline__ int idx_from_hw(int v) {
    return (v <= 1) ? v : 2 + ((v - 7) >> 3) * 3 + ((v - 7) & 7);
}
__device__ __forceinline__ u32 smem_u32(const void* p) {
    u32 a;
    asm("{ .reg .u64 t; cvta.to.shared.u64 t, %1; cvt.u32.u64 %0, t; }" : "=r"(a) : "l"(p));
    return a;
}

// ---------------- mma.sync helpers ----------------
__device__ __forceinline__ void ldm_x4(u32* r, u32 addr) {
    asm volatile("ldmatrix.sync.aligned.m8n8.x4.shared.b16 {%0,%1,%2,%3}, [%4];"
        : "=r"(r[0]), "=r"(r[1]), "=r"(r[2]), "=r"(r[3]) : "r"(addr));
}
__device__ __forceinline__ void ldm_x4t(u32* r, u32 addr) {
    asm volatile("ldmatrix.sync.aligned.m8n8.x4.trans.shared.b16 {%0,%1,%2,%3}, [%4];"
        : "=r"(r[0]), "=r"(r[1]), "=r"(r[2]), "=r"(r[3]) : "r"(addr));
}
__device__ __forceinline__ void mma_bf16(float* c, const u32* a, const u32* b) {
    asm volatile("mma.sync.aligned.m16n8k16.row.col.f32.bf16.bf16.f32 "
        "{%0,%1,%2,%3}, {%4,%5,%6,%7}, {%8,%9}, {%0,%1,%2,%3};"
        : "+f"(c[0]), "+f"(c[1]), "+f"(c[2]), "+f"(c[3])
        : "r"(a[0]), "r"(a[1]), "r"(a[2]), "r"(a[3]), "r"(b[0]), "r"(b[1]));
}
__device__ __forceinline__ void split_store(__nv_bfloat16* hi, __nv_bfloat16* lo,
                                            size_t idx, float2 v) {
    __nv_bfloat162 h = __floats2bfloat162_rn(v.x, v.y);
    __nv_bfloat162 l = __floats2bfloat162_rn(v.x - __bfloat162float(h.x),
                                             v.y - __bfloat162float(h.y));
    *(__nv_bfloat162*)(hi + idx) = h;
    *(__nv_bfloat162*)(lo + idx) = l;
}
__device__ __forceinline__ u32 pack_hi(float a, float b, u32& lo) {
    __nv_bfloat162 h = __floats2bfloat162_rn(a, b);
    __nv_bfloat162 l = __floats2bfloat162_rn(a - __bfloat162float(h.x),
                                             b - __bfloat162float(h.y));
    lo = *(u32*)&l;
    return *(u32*)&h;
}
__device__ __forceinline__ void cpa16(u32 dst, const void* src, int srcsize) {
    asm volatile("cp.async.cg.shared.global [%0], [%1], 16, %2;"
        :: "r"(dst), "l"(src), "r"(srcsize));
}
#define CP_COMMIT() asm volatile("cp.async.commit_group;" ::: "memory")
#define CP_WAIT0()  asm volatile("cp.async.wait_group 0;" ::: "memory")

// ---------------- presplit: x / qkv_w / proj_w -> bf16 hi/lo ----------------
__global__ void presplit_kernel(const float* __restrict__ x,
                                const float* __restrict__ qkv_w,
                                const float* __restrict__ proj_w, int nx)
{
    int i = blockIdx.x * 256 + threadIdx.x;   // float2 pair index
    const int nqkv = 576 * 96 / 2;
    const int nproj = 192 * 192 / 2;
    const float* src;
    __nv_bfloat16 *dh, *dl;
    int off;
    if (i < nx)                   { src = x;      dh = g_xh;  dl = g_xl;  off = i; }
    else if (i < nx + nqkv)       { src = qkv_w;  dh = g_wh;  dl = g_wl;  off = i - nx; }
    else if (i < nx + nqkv + nproj) { src = proj_w; dh = g_pwh; dl = g_pwl; off = i - nx - nqkv; }
    else return;
    float2 v = ((const float2*)src)[off];
    split_store(dh, dl, (size_t)(2 * off), v);
}

// ============================================================================
// cp.async double-buffered bf16 tensor-core GEMM, out[M,192] = A @ B^T + bias
// ============================================================================
#define STG_BYTES 51200
#define STG_AL 10240
#define STG_B  20480
#define STG_BL 15360
#define GEMM_SMEM (2 * STG_BYTES)

__global__ void __launch_bounds__(256) gemm_bf16(
    const float* __restrict__ bias_all, float* __restrict__ outp,
    int Mq, int Mkv, int K, int nbQ, int nbKV, int fused)
{
    extern __shared__ char sm[];
    u32 smb = smem_u32(sm);

    int tid = threadIdx.x;
    int warp = tid >> 5, lane = tid & 31;
    int rm = (warp & 3) * 32;
    int cn = (warp >> 2) * 96;

    const __nv_bfloat16 *Asrc_h, *Asrc_l, *Bsrc_h, *Bsrc_l;
    const float* bp;
    float* out;
    int r0, Mloc;
    bool gather = false;
    if (!fused) {
        Asrc_h = g_aoh; Asrc_l = g_aol; Bsrc_h = g_pwh; Bsrc_l = g_pwl;
        bp = bias_all; out = outp; r0 = blockIdx.x * 128; Mloc = Mq;
    } else if ((int)blockIdx.x < nbQ) {
        Asrc_h = g_xh; Asrc_l = g_xl; Bsrc_h = g_wh; Bsrc_l = g_wl;
        bp = bias_all; out = (float*)g_q; r0 = blockIdx.x * 128; Mloc = Mq;
    } else {
        int t = blockIdx.x - nbQ;
        int sel = t / nbKV, bx2 = t - sel * nbKV;
        gather = true;
        Asrc_h = g_xh; Asrc_l = g_xl;
        Bsrc_h = g_wh + (size_t)(1 + sel) * 192 * 96;
        Bsrc_l = g_wl + (size_t)(1 + sel) * 192 * 96;
        bp = bias_all + (1 + sel) * 192;
        out = sel ? (float*)g_v : (float*)g_k;
        r0 = bx2 * 128; Mloc = Mkv;
    }

    size_t aoff[4];
    int asz[4];
    #pragma unroll
    for (int k4 = 0; k4 < 4; ++k4) {
        int l = tid + k4 * 256;
        int row = l >> 3;
        int r = r0 + row;
        if (r < Mloc) {
            asz[k4] = 16;
            if (gather) {
                int b = r / NKV, ci = r - b * NKV;
                int n = 0;
                if (ci > 0) {
                    int cc = ci - 1;
                    int it = cc / 400, rem = cc - it * 400;
                    int h = hw_from_idx(rem / 20), wv = hw_from_idx(rem % 20);
                    n = 1 + (it * H_IN + h) * W_IN + wv;
                }
                aoff[k4] = ((size_t)b * N_IN + n) * 96;
            } else {
                aoff[k4] = (size_t)r * K;
            }
        } else { aoff[k4] = 0; asz[k4] = 0; }
    }

    float C[2][12][4];
    #pragma unroll
    for (int mt = 0; mt < 2; ++mt)
        #pragma unroll
        for (int nt = 0; nt < 12; ++nt)
            #pragma unroll
            for (int i = 0; i < 4; ++i) C[mt][nt][i] = 0.f;

    int nch = K / 32;

    #define ISSUE_CHUNK(c_, st_) do {                                          \
        int kc = (c_) * 32;                                                    \
        u32 sb = smb + (st_) * STG_BYTES;                                      \
        _Pragma("unroll")                                                      \
        for (int k4 = 0; k4 < 4; ++k4) {                                       \
            int l = tid + k4 * 256;                                            \
            int row = l >> 3, hl = (l >> 2) & 1, seg = l & 3;                  \
            u32 dst = sb + hl * STG_AL + (u32)row * 80u + (u32)seg * 16u;      \
            const __nv_bfloat16* s0 = hl ? Asrc_l : Asrc_h;                    \
            cpa16(dst, s0 + aoff[k4] + kc + seg * 8, asz[k4]);                 \
        }                                                                      \
        _Pragma("unroll")                                                      \
        for (int k6 = 0; k6 < 6; ++k6) {                                       \
            int l = tid + k6 * 256;                                            \
            int row = l >> 3, hl = (l >> 2) & 1, seg = l & 3;                  \
            u32 dst = sb + STG_B + hl * STG_BL + (u32)row * 80u + (u32)seg * 16u; \
            const __nv_bfloat16* s0 = hl ? Bsrc_l : Bsrc_h;                    \
            cpa16(dst, s0 + (size_t)row * K + kc + seg * 8, 16);               \
        }                                                                      \
        CP_COMMIT();                                                           \
    } while (0)

    ISSUE_CHUNK(0, 0);

    for (int c = 0; c < nch; ++c) {
        int st = c & 1;
        if (c + 1 < nch) {
            ISSUE_CHUNK(c + 1, st ^ 1);
            asm volatile("cp.async.wait_group 1;" ::: "memory");
        } else {
            CP_WAIT0();
        }
        __syncthreads();

        u32 sb = smb + st * STG_BYTES;
        #pragma unroll
        for (int ks = 0; ks < 2; ++ks) {
            int k0 = ks * 16;
            u32 ah[2][4], al[2][4];
            #pragma unroll
            for (int mt = 0; mt < 2; ++mt) {
                u32 off = (u32)(rm + mt * 16 + (lane & 15)) * 80u
                        + (u32)(k0 + ((lane >> 4) << 3)) * 2u;
                ldm_x4(ah[mt], sb + off);
                ldm_x4(al[mt], sb + STG_AL + off);
            }
            #pragma unroll
            for (int np = 0; np < 6; ++np) {
                u32 off = (u32)(cn + np * 16 + ((lane >> 4) << 3) + (lane & 7)) * 80u
                        + (u32)(k0 + (((lane >> 3) & 1) << 3)) * 2u;
                u32 bh4[4], bl4[4];
                ldm_x4(bh4, sb + STG_B + off);
                ldm_x4(bl4, sb + STG_B + STG_BL + off);
                #pragma unroll
                for (int mt = 0; mt < 2; ++mt) {
                    mma_bf16(C[mt][2 * np],     ah[mt], bh4);
                    mma_bf16(C[mt][2 * np],     ah[mt], bl4);
                    mma_bf16(C[mt][2 * np],     al[mt], bh4);
                    mma_bf16(C[mt][2 * np + 1], ah[mt], bh4 + 2);
                    mma_bf16(C[mt][2 * np + 1], ah[mt], bl4 + 2);
                    mma_bf16(C[mt][2 * np + 1], al[mt], bh4 + 2);
                }
            }
        }
        __syncthreads();
    }

    int gr = lane >> 2;
    int gc = (lane & 3) * 2;
    #pragma unroll
    for (int mt = 0; mt < 2; ++mt) {
        int row0 = r0 + rm + mt * 16 + gr;
        int row1 = row0 + 8;
        #pragma unroll
        for (int nt = 0; nt < 12; ++nt) {
            int col = cn + nt * 8 + gc;
            float b0 = bp[col], b1 = bp[col + 1];
            if (row0 < Mloc) {
                float2 o = make_float2(C[mt][nt][0] + b0, C[mt][nt][1] + b1);
                *(float2*)&out[(size_t)row0 * 192 + col] = o;
            }
            if (row1 < Mloc) {
                float2 o = make_float2(C[mt][nt][2] + b0, C[mt][nt][3] + b1);
                *(float2*)&out[(size_t)row1 * 192 + col] = o;
            }
        }
    }
}

// ---------------- LN helper (96 threads) ----------------
__device__ __forceinline__ float ln96(float val, const float* gg, const float* bb, int c,
                                      float* p1, float* p2, float* mv)
{
    float s1 = val, s2 = val * val;
    #pragma unroll
    for (int off = 16; off > 0; off >>= 1) {
        s1 += __shfl_xor_sync(0xffffffffu, s1, off);
        s2 += __shfl_xor_sync(0xffffffffu, s2, off);
    }
    int wid = c >> 5, lane = c & 31;
    if (lane == 0) { p1[wid] = s1; p2[wid] = s2; }
    __syncthreads();
    if (c == 0) {
        float t1 = p1[0] + p1[1] + p1[2];
        float t2 = p2[0] + p2[1] + p2[2];
        float mean = t1 / 96.f;
        float var  = t2 / 96.f - mean * mean;
        mv[0] = mean; mv[1] = rsqrtf(var + 1e-5f);
    }
    __syncthreads();
    return (val - mv[0]) * mv[1] * gg[c] + bb[c];
}

// ---------------- Q pool: register plane-sums; cls folded in ----------------
__global__ void pool_q_kernel(const float* __restrict__ cw, const float* __restrict__ gg,
                              const float* __restrict__ bb, int nSpatial)
{
    __shared__ float p1[3], p2[3], mv[2];
    int o = blockIdx.x;
    int c = threadIdx.x;

    if (o >= nSpatial) {
        int idx = o - nSpatial;
        int head = idx & 1, b = idx >> 1;
        float val = g_q[((size_t)b * N_IN) * 192 + head * 96 + c];
        float outv = ln96(val, gg, bb, c, p1, p2, mv);
        g_qp[((size_t)((b * 2 + head) * QN)) * 96 + c] = outv;
        return;
    }

    int w2 = o % QW;
    int h2 = (o / QW) % QH;
    int head = (o / (QW * QH)) & 1;
    int b = o / (QW * QH * 2);

    float wreg[27];
    #pragma unroll
    for (int t = 0; t < 27; ++t) wreg[t] = cw[c * 27 + t];

    float ps[8][3];
    #pragma unroll
    for (int it = 0; it < 8; ++it)
        #pragma unroll
        for (int d = 0; d < 3; ++d) ps[it][d] = 0.f;

    const float* base = g_q + ((size_t)(b * N_IN + 1)) * 192 + head * 96 + c;
    #pragma unroll
    for (int dh = 0; dh < 3; ++dh) {
        int ih = 2 * h2 - 1 + dh;
        if (ih < 0 || ih >= H_IN) continue;
        #pragma unroll
        for (int dw = 0; dw < 3; ++dw) {
            int iw = 2 * w2 - 1 + dw;
            if (iw < 0 || iw >= W_IN) continue;
            float w0 = wreg[(0 * 3 + dh) * 3 + dw];
            float w1 = wreg[(1 * 3 + dh) * 3 + dw];
            float w2r = wreg[(2 * 3 + dh) * 3 + dw];
            #pragma unroll
            for (int it = 0; it < 8; ++it) {
                int tok = (it * H_IN + ih) * W_IN + iw;
                float v = base[(size_t)tok * 192];
                ps[it][0] = fmaf(w0, v, ps[it][0]);
                ps[it][1] = fmaf(w1, v, ps[it][1]);
                ps[it][2] = fmaf(w2r, v, ps[it][2]);
            }
        }
    }

    for (int t2 = 0; t2 < QT; ++t2) {
        float s = ps[t2][1];
        if (t2 > 0) s += ps[t2 - 1][0];
        if (t2 < 7) s += ps[t2 + 1][2];
        float outv = ln96(s, gg, bb, c, p1, p2, mv);
        int n = 1 + (t2 * QH + h2) * QW + w2;
        g_qp[((size_t)((b * 2 + head) * QN) + n) * 96 + c] = outv;
        __syncthreads();
    }
}

// ---------------- K/V pool + LN -> pre-split bf16 hi/lo outputs ----------------
__global__ void pool_kv_kernel(const float* __restrict__ cwk, const float* __restrict__ ggk,
                               const float* __restrict__ bbk,
                               const float* __restrict__ cwv, const float* __restrict__ ggv,
                               const float* __restrict__ bbv)
{
    __shared__ float p1[3], p2[3], mv[2];
    int whichV = blockIdx.y;
    const float* cw = whichV ? cwv : cwk;
    const float* gg = whichV ? ggv : ggk;
    const float* bb = whichV ? bbv : bbk;
    int o    = blockIdx.x;
    int n    = o % KN;
    int head = (o / KN) & 1;
    int b    = o / (KN * 2);
    int c    = threadIdx.x;

    const float* src = whichV ? g_v : g_k;

    float val;
    if (n == 0) {
        val = src[((size_t)b * NKV) * 192 + head * 96 + c];
    } else {
        int tn  = n - 1;
        int t2  = tn / (KH * KW);
        int rem = tn % (KH * KW);
        int h2  = rem / KW, w2 = rem % KW;
        float s = 0.f;
        #pragma unroll
        for (int dt = 0; dt < 3; ++dt) {
            int it = t2 + dt - 1;
            if (it < 0 || it >= T_IN) continue;
            #pragma unroll
            for (int dh = 0; dh < 3; ++dh) {
                int ih = h2 * 8 + dh - 1;
                if (ih < 0 || ih >= H_IN) continue;
                #pragma unroll
                for (int dw = 0; dw < 3; ++dw) {
                    int iw = w2 * 8 + dw - 1;
                    if (iw < 0 || iw >= W_IN) continue;
                    int ci = 1 + (it * 20 + idx_from_hw(ih)) * 20 + idx_from_hw(iw);
                    s = fmaf(cw[c * 27 + (dt * 3 + dh) * 3 + dw],
                             src[((size_t)(b * NKV + ci)) * 192 + head * 96 + c], s);
                }
            }
        }
        val = s;
    }
    float outv = ln96(val, gg, bb, c, p1, p2, mv);
    size_t oidx = ((size_t)((b * 2 + head) * KN) + n) * 96 + c;
    __nv_bfloat16 h = __float2bfloat16(outv);
    __nv_bfloat16 l = __float2bfloat16(outv - __bfloat162float(h));
    if (whichV) { g_vph[oidx] = h; g_vpl[oidx] = l; }
    else        { g_kph[oidx] = h; g_kpl[oidx] = l; }
}

// ============================================================================
// FA2-style attention: 128 q-rows/block, 8 warps x 16 rows, register P,
// cp.async staging from pre-split bf16 K/V
// ============================================================================
#define ASM_KH   0
#define ASM_KL   13312
#define ASM_VH   26624
#define ASM_VL   39936
#define ASM_SREL 53248
#define ASM_JMAP 65536
#define ATTN_SMEM2 67328

__global__ void __launch_bounds__(256) attn_fa2_kernel(
    const float* __restrict__ rph, const float* __restrict__ rpw,
    const float* __restrict__ rpt)
{
    extern __shared__ char sm[];
    float* Qf = (float*)sm;   // [128][100] fp32, phase 1 only (overlaid by K/V)
    float* srel = (float*)(sm + ASM_SREL);   // [128][24]
    u32* jmap = (u32*)(sm + ASM_JMAP);       // [448]
    u32 smb = smem_u32(sm);

    int tid = threadIdx.x;
    int warp = tid >> 5, lane = tid & 31;
    int gr = lane >> 2;
    int wr0 = warp * 16;
    int bh = blockIdx.y;
    int q0 = blockIdx.x * 128;
    const float* qp = g_qp + (size_t)bh * QN * 96;
    const __nv_bfloat16* kvsrc[4] = {
        g_kph + (size_t)bh * KN * 96, g_kpl + (size_t)bh * KN * 96,
        g_vph + (size_t)bh * KN * 96, g_vpl + (size_t)bh * KN * 96 };

    // ---- phase 1: stage Q fp32 via cp.async (stride 100 floats = 400B) ----
    #pragma unroll
    for (int k12 = 0; k12 < 12; ++k12) {
        int l = tid + k12 * 256;          // 128 rows x 24 segs
        int row = l / 24, seg = l - row * 24;
        int qr = q0 + row;
        u32 dst = smb + (u32)row * 400u + (u32)seg * 16u;
        cpa16(dst, qp + (size_t)qr * 96 + seg * 4, (qr < QN) ? 16 : 0);
    }
    CP_COMMIT();
    for (int j = tid; j < 448; j += 256) {
        u32 m = 0xFFFFFFFFu;
        if (j > 0 && j < KN) {
            int kk = j - 1, kt = kk / 49, rm = kk % 49;
            m = (u32)kt | ((u32)(rm / 7) << 8) | ((u32)(rm % 7) << 16);
        }
        jmap[j] = m;
    }
    CP_WAIT0();
    __syncthreads();

    // ---- rel-pos dots ----
    for (int idx = tid; idx < 128 * 22; idx += 256) {
        int qi = idx / 22, r = idx - qi * 22;
        int qr = q0 + qi;
        float s = 0.f;
        if (qr > 0 && qr < QN) {
            int tok = qr - 1;
            int tq = tok / (QH * QW);
            int hq = (tok / QW) % QH;
            int wq = tok % QW;
            const float* tab;
            if (r < 8)       tab = rpt + (size_t)(tq - r + 7) * 96;
            else if (r < 15) tab = rph + (size_t)(hq - 4 * (r - 8) + 24) * 96;
            else             tab = rpw + (size_t)(wq - 4 * (r - 15) + 24) * 96;
            #pragma unroll 4
            for (int k = 0; k < 96; ++k) s = fmaf(Qf[qi * 100 + k], tab[k], s);
        }
        srel[qi * 24 + r] = s;
    }

    // ---- Q a-fragments (hi/lo), loaded once ----
    u32 qh[6][4], ql[6][4];
    {
        int rA = wr0 + gr;
        int c2 = 2 * (lane & 3);
        #pragma unroll
        for (int ks = 0; ks < 6; ++ks) {
            int kb = ks * 16;
            float2 v0 = *(const float2*)&Qf[rA * 100 + kb + c2];
            float2 v1 = *(const float2*)&Qf[(rA + 8) * 100 + kb + c2];
            float2 v2 = *(const float2*)&Qf[rA * 100 + kb + 8 + c2];
            float2 v3 = *(const float2*)&Qf[(rA + 8) * 100 + kb + 8 + c2];
            qh[ks][0] = pack_hi(v0.x, v0.y, ql[ks][0]);
            qh[ks][1] = pack_hi(v1.x, v1.y, ql[ks][1]);
            qh[ks][2] = pack_hi(v2.x, v2.y, ql[ks][2]);
            qh[ks][3] = pack_hi(v3.x, v3.y, ql[ks][3]);
        }
    }

    int qrA = q0 + wr0 + gr;
    int qrB = qrA + 8;
    bool relA = (qrA > 0 && qrA < QN);
    bool relB = (qrB > 0 && qrB < QN);
    const float* srelA = srel + (wr0 + gr) * 24;
    const float* srelB = srelA + 8 * 24;

    float O[12][4];
    #pragma unroll
    for (int nt = 0; nt < 12; ++nt)
        #pragma unroll
        for (int i = 0; i < 4; ++i) O[nt][i] = 0.f;
    float sumA = 0.f, sumB = 0.f;

    for (int ch = 0; ch < 7; ++ch) {
        int j0 = ch * 64;
        __syncthreads();   // prev chunk fully consumed (and Qf reads done on ch=0)
        // stage K/V hi+lo via cp.async: 4 bufs x 64 rows x 12 segs = 3072 x 16B
        #pragma unroll
        for (int k12 = 0; k12 < 12; ++k12) {
            int l = tid + k12 * 256;
            int buf = l / 768, rem = l - buf * 768;
            int row = rem / 12, seg = rem - row * 12;
            int j = j0 + row;
            u32 dst = smb + (u32)buf * 13312u + (u32)row * 208u + (u32)seg * 16u;
            cpa16(dst, kvsrc[buf] + (size_t)j * 96 + seg * 8, (j < KN) ? 16 : 0);
        }
        CP_COMMIT();
        CP_WAIT0();
        __syncthreads();

        // ---- QK^T -> S (16 x 64 per warp) ----
        float S[8][4];
        #pragma unroll
        for (int jt = 0; jt < 8; ++jt)
            #pragma unroll
            for (int i = 0; i < 4; ++i) S[jt][i] = 0.f;

        #pragma unroll
        for (int ks = 0; ks < 6; ++ks) {
            #pragma unroll
            for (int jt2 = 0; jt2 < 4; ++jt2) {
                u32 addr = smb + ASM_KH
                         + (u32)(jt2 * 16 + ((lane >> 4) << 3) + (lane & 7)) * 208u
                         + (u32)(ks * 16 + ((lane >> 3) & 1) * 8) * 2u;
                u32 bh4[4], bl4[4];
                ldm_x4(bh4, addr);
                ldm_x4(bl4, addr + (ASM_KL - ASM_KH));
                mma_bf16(S[2 * jt2],     qh[ks], bh4);
                mma_bf16(S[2 * jt2],     qh[ks], bl4);
                mma_bf16(S[2 * jt2],     ql[ks], bh4);
                mma_bf16(S[2 * jt2 + 1], qh[ks], bh4 + 2);
                mma_bf16(S[2 * jt2 + 1], qh[ks], bl4 + 2);
                mma_bf16(S[2 * jt2 + 1], ql[ks], bh4 + 2);
            }
        }

        // ---- exp + rel-pos in registers ----
        #pragma unroll
        for (int jt = 0; jt < 8; ++jt) {
            #pragma unroll
            for (int e = 0; e < 4; ++e) {
                int j = j0 + jt * 8 + 2 * (lane & 3) + (e & 1);
                float ev = 0.f;
                if (j < KN) {
                    float s = S[jt][e] * ATTN_SCALE;
                    bool rr = (e < 2) ? relA : relB;
                    u32 m = jmap[j];
                    if (rr && m != 0xFFFFFFFFu) {
                        const float* sr = (e < 2) ? srelA : srelB;
                        s += sr[m & 0xFF] + sr[8 + ((m >> 8) & 0xFF)]
                           + sr[15 + ((m >> 16) & 0xFF)];
                    }
                    ev = __expf(s);
                    if (e < 2) sumA += ev; else sumB += ev;
                }
                S[jt][e] = ev;
            }
        }

        // ---- repack S as P a-fragments (hi/lo) ----
        u32 ph[4][4], pl[4][4];
        #pragma unroll
        for (int t = 0; t < 4; ++t) {
            ph[t][0] = pack_hi(S[2 * t][0],     S[2 * t][1],     pl[t][0]);
            ph[t][1] = pack_hi(S[2 * t][2],     S[2 * t][3],     pl[t][1]);
            ph[t][2] = pack_hi(S[2 * t + 1][0], S[2 * t + 1][1], pl[t][2]);
            ph[t][3] = pack_hi(S[2 * t + 1][2], S[2 * t + 1][3], pl[t][3]);
        }

        // ---- P @ V ----
        #pragma unroll
        for (int kt = 0; kt < 4; ++kt) {
            #pragma unroll
            for (int nt2 = 0; nt2 < 6; ++nt2) {
                u32 addr = smb + ASM_VH
                         + (u32)(kt * 16 + ((lane >> 3) & 1) * 8 + (lane & 7)) * 208u
                         + (u32)(nt2 * 16 + ((lane >> 4) << 3)) * 2u;
                u32 vh4[4], vl4[4];
                ldm_x4t(vh4, addr);
                ldm_x4t(vl4, addr + (ASM_VL - ASM_VH));
                mma_bf16(O[2 * nt2],     ph[kt], vh4);
                mma_bf16(O[2 * nt2],     ph[kt], vl4);
                mma_bf16(O[2 * nt2],     pl[kt], vh4);
                mma_bf16(O[2 * nt2 + 1], ph[kt], vh4 + 2);
                mma_bf16(O[2 * nt2 + 1], ph[kt], vl4 + 2);
                mma_bf16(O[2 * nt2 + 1], pl[kt], vh4 + 2);
            }
        }
    }

    // ---- row sums: reduce over the 4 quad lanes ----
    sumA += __shfl_xor_sync(0xffffffffu, sumA, 1);
    sumA += __shfl_xor_sync(0xffffffffu, sumA, 2);
    sumB += __shfl_xor_sync(0xffffffffu, sumB, 1);
    sumB += __shfl_xor_sync(0xffffffffu, sumB, 2);
    float riA = 1.f / sumA;
    float riB = 1.f / sumB;

    // ---- epilogue: normalize + residual + store as bf16 hi/lo ----
    int b = bh >> 1, head = bh & 1;
    int c2 = 2 * (lane & 3);
    if (qrA < QN) {
        #pragma unroll
        for (int nt = 0; nt < 12; ++nt) {
            int col = nt * 8 + c2;
            float2 qv = *(const float2*)&qp[(size_t)qrA * 96 + col];
            float2 o = make_float2(O[nt][0] * riA + qv.x, O[nt][1] * riA + qv.y);
            split_store(g_aoh, g_aol,
                        ((size_t)(b * QN + qrA)) * 192 + head * 96 + col, o);
        }
    }
    if (qrB < QN) {
        #pragma unroll
        for (int nt = 0; nt < 12; ++nt) {
            int col = nt * 8 + c2;
            float2 qv = *(const float2*)&qp[(size_t)qrB * 96 + col];
            float2 o = make_float2(O[nt][2] * riB + qv.x, O[nt][3] * riB + qv.y);
            split_store(g_aoh, g_aol,
                        ((size_t)(b * QN + qrB)) * 192 + head * 96 + col, o);
        }
    }
}

// ---------------- launch ----------------
extern "C" void kernel_launch(void* const* d_in, const int* in_sizes, int n_in,
                              void* d_out, int out_size)
{
    const float* x      = (const float*)d_in[0];
    const float* qkv_w  = (const float*)d_in[1];
    const float* qkv_b  = (const float*)d_in[2];
    const float* proj_w = (const float*)d_in[3];
    const float* proj_b = (const float*)d_in[4];
    const float* pq_w   = (const float*)d_in[5];
    const float* nq_g   = (const float*)d_in[6];
    const float* nq_b   = (const float*)d_in[7];
    const float* pk_w   = (const float*)d_in[8];
    const float* nk_g   = (const float*)d_in[9];
    const float* nk_b   = (const float*)d_in[10];
    const float* pv_w   = (const float*)d_in[11];
    const float* nv_g   = (const float*)d_in[12];
    const float* nv_b   = (const float*)d_in[13];
    const float* rph    = (const float*)d_in[14];
    const float* rpw    = (const float*)d_in[15];
    const float* rpt    = (const float*)d_in[16];

    int B = in_sizes[0] / (N_IN * 96);
    if (B > B_MAX) B = B_MAX;
    int M   = B * N_IN;
    int Mkv = B * NKV;
    int nbQ  = (M + 127) / 128;
    int nbKV = (Mkv + 127) / 128;

    cudaFuncSetAttribute(gemm_bf16, cudaFuncAttributeMaxDynamicSharedMemorySize, GEMM_SMEM);
    cudaFuncSetAttribute(attn_fa2_kernel, cudaFuncAttributeMaxDynamicSharedMemorySize, ATTN_SMEM2);

    int nx = M * 48;   // float2 pairs in x
    int totalPairs = nx + 576 * 96 / 2 + 192 * 192 / 2;
    presplit_kernel<<<(totalPairs + 255) / 256, 256>>>(x, qkv_w, proj_w, nx);

    gemm_bf16<<<nbQ + 2 * nbKV, 256, GEMM_SMEM>>>(qkv_b, nullptr, M, Mkv, 96, nbQ, nbKV, 1);

    int nSpatial = B * 2 * QH * QW;
    pool_q_kernel<<<nSpatial + B * 2, 96>>>(pq_w, nq_g, nq_b, nSpatial);
    pool_kv_kernel<<<dim3(B * 2 * KN, 2), 96>>>(pk_w, nk_g, nk_b, pv_w, nv_g, nv_b);
    attn_fa2_kernel<<<dim3((QN + 127) / 128, B * 2), 256, ATTN_SMEM2>>>(rph, rpw, rpt);

    gemm_bf16<<<(B * QN + 127) / 128, 256, GEMM_SMEM>>>(proj_b, (float*)d_out,
                                                        B * QN, 0, 192, 0, 0, 0);
}

// round 11
// speedup vs baseline: 1.7966x; 1.0727x over previous
#include <cuda_runtime.h>
#include <cuda_bf16.h>
#include <math.h>

typedef unsigned long long u64;
typedef unsigned int u32;

#define B_MAX 4
#define N_IN 25089      // 1 + 8*56*56
#define T_IN 8
#define H_IN 56
#define W_IN 56
#define QT 8
#define QH 28
#define QW 28
#define QN 6273         // 1 + 8*28*28
#define KT 8
#define KH 7
#define KW 7
#define KN 393          // 1 + 8*7*7
#define KNP 448         // padded key count
#define NKV 3201        // 1 + 8*20*20 gathered tokens per batch
#define ATTN_SCALE 0.102062072615965745f   // 1/sqrt(96)

// ---------------- scratch (device globals; no allocation) ----------------
__device__ float g_q [(size_t)B_MAX * N_IN * 192];
__device__ float g_k [(size_t)B_MAX * NKV * 192];
__device__ float g_v [(size_t)B_MAX * NKV * 192];
__device__ float g_qp[(size_t)B_MAX * 2 * QN * 96];
// bf16 hi/lo pre-split tensors
__device__ __nv_bfloat16 g_xh[(size_t)B_MAX * N_IN * 96];
__device__ __nv_bfloat16 g_xl[(size_t)B_MAX * N_IN * 96];
__device__ __nv_bfloat16 g_wh[576 * 96];
__device__ __nv_bfloat16 g_wl[576 * 96];
__device__ __nv_bfloat16 g_pwh[192 * 192];
__device__ __nv_bfloat16 g_pwl[192 * 192];
__device__ __nv_bfloat16 g_aoh[(size_t)B_MAX * QN * 192];
__device__ __nv_bfloat16 g_aol[(size_t)B_MAX * QN * 192];
// extended pooled K (128 cols: 96 ch + 22 onehot + mask + pad) and pooled V
__device__ __nv_bfloat16 g_keh[(size_t)B_MAX * 2 * KNP * 128];
__device__ __nv_bfloat16 g_kel[(size_t)B_MAX * 2 * KNP * 128];
__device__ __nv_bfloat16 g_vph[(size_t)B_MAX * 2 * KN * 96];
__device__ __nv_bfloat16 g_vpl[(size_t)B_MAX * 2 * KN * 96];

// ---------------- helpers ----------------
__device__ __forceinline__ int hw_from_idx(int i) {
    return (i < 2) ? i : 7 + ((i - 2) / 3) * 8 + ((i - 2) % 3);
}
__device__ __forceinline__ u32 smem_u32(const void* p) {
    u32 a;
    asm("{ .reg .u64 t; cvta.to.shared.u64 t, %1; cvt.u32.u64 %0, t; }" : "=r"(a) : "l"(p));
    return a;
}
// f32x2 packed helpers
__device__ __forceinline__ u64 fma2o(u64 a, u64 b, u64 c) {
    u64 d; asm("fma.rn.f32x2 %0, %1, %2, %3;" : "=l"(d) : "l"(a), "l"(b), "l"(c)); return d;
}
__device__ __forceinline__ u64 add2(u64 a, u64 b) {
    u64 d; asm("add.rn.f32x2 %0, %1, %2;" : "=l"(d) : "l"(a), "l"(b)); return d;
}
__device__ __forceinline__ u64 mul2(u64 a, u64 b) {
    u64 d; asm("mul.rn.f32x2 %0, %1, %2;" : "=l"(d) : "l"(a), "l"(b)); return d;
}
__device__ __forceinline__ u64 dupf(float v) {
    u64 r; asm("mov.b64 %0, {%1, %1};" : "=l"(r) : "f"(v)); return r;
}
__device__ __forceinline__ float2 u2f(u64 v) {
    float2 r; asm("mov.b64 {%0, %1}, %2;" : "=f"(r.x), "=f"(r.y) : "l"(v)); return r;
}
// packed fast exp: e^x for two lanes, poly deg-4, rel err ~4e-5
__device__ __forceinline__ u64 fexp2(float a, float b) {
    u64 x2; asm("mov.b64 %0, {%1, %2};" : "=l"(x2) : "f"(a), "f"(b));
    u64 t2 = fma2o(x2, dupf(1.4426950408889634f), dupf(12582912.f));
    u64 n2 = add2(t2, dupf(-12582912.f));
    u64 r2 = fma2o(n2, dupf(-0.6931471805599453f), x2);
    u64 p2 = fma2o(r2, dupf(4.1666667e-2f), dupf(1.6666667e-1f));
    p2 = fma2o(p2, r2, dupf(0.5f));
    p2 = fma2o(p2, r2, dupf(1.0f));
    p2 = fma2o(p2, r2, dupf(1.0f));
    u32 tl = (u32)t2, th = (u32)(t2 >> 32);
    u32 sl = (tl << 23) + 0x3f800000u;
    u32 sh = (th << 23) + 0x3f800000u;
    u64 s2 = ((u64)sh << 32) | (u64)sl;
    return mul2(p2, s2);
}

// ---------------- mma.sync helpers ----------------
__device__ __forceinline__ void ldm_x4(u32* r, u32 addr) {
    asm volatile("ldmatrix.sync.aligned.m8n8.x4.shared.b16 {%0,%1,%2,%3}, [%4];"
        : "=r"(r[0]), "=r"(r[1]), "=r"(r[2]), "=r"(r[3]) : "r"(addr));
}
__device__ __forceinline__ void ldm_x4t(u32* r, u32 addr) {
    asm volatile("ldmatrix.sync.aligned.m8n8.x4.trans.shared.b16 {%0,%1,%2,%3}, [%4];"
        : "=r"(r[0]), "=r"(r[1]), "=r"(r[2]), "=r"(r[3]) : "r"(addr));
}
__device__ __forceinline__ void mma_bf16(float* c, const u32* a, const u32* b) {
    asm volatile("mma.sync.aligned.m16n8k16.row.col.f32.bf16.bf16.f32 "
        "{%0,%1,%2,%3}, {%4,%5,%6,%7}, {%8,%9}, {%0,%1,%2,%3};"
        : "+f"(c[0]), "+f"(c[1]), "+f"(c[2]), "+f"(c[3])
        : "r"(a[0]), "r"(a[1]), "r"(a[2]), "r"(a[3]), "r"(b[0]), "r"(b[1]));
}
__device__ __forceinline__ void split_store(__nv_bfloat16* hi, __nv_bfloat16* lo,
                                            size_t idx, float2 v) {
    __nv_bfloat162 h = __floats2bfloat162_rn(v.x, v.y);
    __nv_bfloat162 l = __floats2bfloat162_rn(v.x - __bfloat162float(h.x),
                                             v.y - __bfloat162float(h.y));
    *(__nv_bfloat162*)(hi + idx) = h;
    *(__nv_bfloat162*)(lo + idx) = l;
}
__device__ __forceinline__ u32 pack_hi(float a, float b, u32& lo) {
    __nv_bfloat162 h = __floats2bfloat162_rn(a, b);
    __nv_bfloat162 l = __floats2bfloat162_rn(a - __bfloat162float(h.x),
                                             b - __bfloat162float(h.y));
    lo = *(u32*)&l;
    return *(u32*)&h;
}
__device__ __forceinline__ void cpa16(u32 dst, const void* src, int srcsize) {
    asm volatile("cp.async.cg.shared.global [%0], [%1], 16, %2;"
        :: "r"(dst), "l"(src), "r"(srcsize));
}
#define CP_COMMIT() asm volatile("cp.async.commit_group;" ::: "memory")
#define CP_WAIT0()  asm volatile("cp.async.wait_group 0;" ::: "memory")

// ---------------- presplit: x / qkv_w / proj_w -> bf16 hi/lo ----------------
__global__ void presplit_kernel(const float* __restrict__ x,
                                const float* __restrict__ qkv_w,
                                const float* __restrict__ proj_w, int nx)
{
    int i = blockIdx.x * 256 + threadIdx.x;
    const int nqkv = 576 * 96 / 2;
    const int nproj = 192 * 192 / 2;
    const float* src;
    __nv_bfloat16 *dh, *dl;
    int off;
    if (i < nx)                   { src = x;      dh = g_xh;  dl = g_xl;  off = i; }
    else if (i < nx + nqkv)       { src = qkv_w;  dh = g_wh;  dl = g_wl;  off = i - nx; }
    else if (i < nx + nqkv + nproj) { src = proj_w; dh = g_pwh; dl = g_pwl; off = i - nx - nqkv; }
    else return;
    float2 v = ((const float2*)src)[off];
    split_store(dh, dl, (size_t)(2 * off), v);
}

// ============================================================================
// cp.async double-buffered bf16 tensor-core GEMM (unchanged from R10)
// ============================================================================
#define STG_BYTES 51200
#define STG_AL 10240
#define STG_B  20480
#define STG_BL 15360
#define GEMM_SMEM (2 * STG_BYTES)

__global__ void __launch_bounds__(256) gemm_bf16(
    const float* __restrict__ bias_all, float* __restrict__ outp,
    int Mq, int Mkv, int K, int nbQ, int nbKV, int fused)
{
    extern __shared__ char sm[];
    u32 smb = smem_u32(sm);

    int tid = threadIdx.x;
    int warp = tid >> 5, lane = tid & 31;
    int rm = (warp & 3) * 32;
    int cn = (warp >> 2) * 96;

    const __nv_bfloat16 *Asrc_h, *Asrc_l, *Bsrc_h, *Bsrc_l;
    const float* bp;
    float* out;
    int r0, Mloc;
    bool gather = false;
    if (!fused) {
        Asrc_h = g_aoh; Asrc_l = g_aol; Bsrc_h = g_pwh; Bsrc_l = g_pwl;
        bp = bias_all; out = outp; r0 = blockIdx.x * 128; Mloc = Mq;
    } else if ((int)blockIdx.x < nbQ) {
        Asrc_h = g_xh; Asrc_l = g_xl; Bsrc_h = g_wh; Bsrc_l = g_wl;
        bp = bias_all; out = (float*)g_q; r0 = blockIdx.x * 128; Mloc = Mq;
    } else {
        int t = blockIdx.x - nbQ;
        int sel = t / nbKV, bx2 = t - sel * nbKV;
        gather = true;
        Asrc_h = g_xh; Asrc_l = g_xl;
        Bsrc_h = g_wh + (size_t)(1 + sel) * 192 * 96;
        Bsrc_l = g_wl + (size_t)(1 + sel) * 192 * 96;
        bp = bias_all + (1 + sel) * 192;
        out = sel ? (float*)g_v : (float*)g_k;
        r0 = bx2 * 128; Mloc = Mkv;
    }

    size_t aoff[4];
    int asz[4];
    #pragma unroll
    for (int k4 = 0; k4 < 4; ++k4) {
        int l = tid + k4 * 256;
        int row = l >> 3;
        int r = r0 + row;
        if (r < Mloc) {
            asz[k4] = 16;
            if (gather) {
                int b = r / NKV, ci = r - b * NKV;
                int n = 0;
                if (ci > 0) {
                    int cc = ci - 1;
                    int it = cc / 400, rem = cc - it * 400;
                    int h = hw_from_idx(rem / 20), wv = hw_from_idx(rem % 20);
                    n = 1 + (it * H_IN + h) * W_IN + wv;
                }
                aoff[k4] = ((size_t)b * N_IN + n) * 96;
            } else {
                aoff[k4] = (size_t)r * K;
            }
        } else { aoff[k4] = 0; asz[k4] = 0; }
    }

    float C[2][12][4];
    #pragma unroll
    for (int mt = 0; mt < 2; ++mt)
        #pragma unroll
        for (int nt = 0; nt < 12; ++nt)
            #pragma unroll
            for (int i = 0; i < 4; ++i) C[mt][nt][i] = 0.f;

    int nch = K / 32;

    #define ISSUE_CHUNK(c_, st_) do {                                          \
        int kc = (c_) * 32;                                                    \
        u32 sb = smb + (st_) * STG_BYTES;                                      \
        _Pragma("unroll")                                                      \
        for (int k4 = 0; k4 < 4; ++k4) {                                       \
            int l = tid + k4 * 256;                                            \
            int row = l >> 3, hl = (l >> 2) & 1, seg = l & 3;                  \
            u32 dst = sb + hl * STG_AL + (u32)row * 80u + (u32)seg * 16u;      \
            const __nv_bfloat16* s0 = hl ? Asrc_l : Asrc_h;                    \
            cpa16(dst, s0 + aoff[k4] + kc + seg * 8, asz[k4]);                 \
        }                                                                      \
        _Pragma("unroll")                                                      \
        for (int k6 = 0; k6 < 6; ++k6) {                                       \
            int l = tid + k6 * 256;                                            \
            int row = l >> 3, hl = (l >> 2) & 1, seg = l & 3;                  \
            u32 dst = sb + STG_B + hl * STG_BL + (u32)row * 80u + (u32)seg * 16u; \
            const __nv_bfloat16* s0 = hl ? Bsrc_l : Bsrc_h;                    \
            cpa16(dst, s0 + (size_t)row * K + kc + seg * 8, 16);               \
        }                                                                      \
        CP_COMMIT();                                                           \
    } while (0)

    ISSUE_CHUNK(0, 0);

    for (int c = 0; c < nch; ++c) {
        int st = c & 1;
        if (c + 1 < nch) {
            ISSUE_CHUNK(c + 1, st ^ 1);
            asm volatile("cp.async.wait_group 1;" ::: "memory");
        } else {
            CP_WAIT0();
        }
        __syncthreads();

        u32 sb = smb + st * STG_BYTES;
        #pragma unroll
        for (int ks = 0; ks < 2; ++ks) {
            int k0 = ks * 16;
            u32 ah[2][4], al[2][4];
            #pragma unroll
            for (int mt = 0; mt < 2; ++mt) {
                u32 off = (u32)(rm + mt * 16 + (lane & 15)) * 80u
                        + (u32)(k0 + ((lane >> 4) << 3)) * 2u;
                ldm_x4(ah[mt], sb + off);
                ldm_x4(al[mt], sb + STG_AL + off);
            }
            #pragma unroll
            for (int np = 0; np < 6; ++np) {
                u32 off = (u32)(cn + np * 16 + ((lane >> 4) << 3) + (lane & 7)) * 80u
                        + (u32)(k0 + (((lane >> 3) & 1) << 3)) * 2u;
                u32 bh4[4], bl4[4];
                ldm_x4(bh4, sb + STG_B + off);
                ldm_x4(bl4, sb + STG_B + STG_BL + off);
                #pragma unroll
                for (int mt = 0; mt < 2; ++mt) {
                    mma_bf16(C[mt][2 * np],     ah[mt], bh4);
                    mma_bf16(C[mt][2 * np],     ah[mt], bl4);
                    mma_bf16(C[mt][2 * np],     al[mt], bh4);
                    mma_bf16(C[mt][2 * np + 1], ah[mt], bh4 + 2);
                    mma_bf16(C[mt][2 * np + 1], ah[mt], bl4 + 2);
                    mma_bf16(C[mt][2 * np + 1], al[mt], bh4 + 2);
                }
            }
        }
        __syncthreads();
    }

    int gr = lane >> 2;
    int gc = (lane & 3) * 2;
    #pragma unroll
    for (int mt = 0; mt < 2; ++mt) {
        int row0 = r0 + rm + mt * 16 + gr;
        int row1 = row0 + 8;
        #pragma unroll
        for (int nt = 0; nt < 12; ++nt) {
            int col = cn + nt * 8 + gc;
            float b0 = bp[col], b1 = bp[col + 1];
            if (row0 < Mloc) {
                float2 o = make_float2(C[mt][nt][0] + b0, C[mt][nt][1] + b1);
                *(float2*)&out[(size_t)row0 * 192 + col] = o;
            }
            if (row1 < Mloc) {
                float2 o = make_float2(C[mt][nt][2] + b0, C[mt][nt][3] + b1);
                *(float2*)&out[(size_t)row1 * 192 + col] = o;
            }
        }
    }
}

// ---------------- LN helper (96 threads) ----------------
__device__ __forceinline__ float ln96(float val, const float* gg, const float* bb, int c,
                                      float* p1, float* p2, float* mv)
{
    float s1 = val, s2 = val * val;
    #pragma unroll
    for (int off = 16; off > 0; off >>= 1) {
        s1 += __shfl_xor_sync(0xffffffffu, s1, off);
        s2 += __shfl_xor_sync(0xffffffffu, s2, off);
    }
    int wid = c >> 5, lane = c & 31;
    if (lane == 0) { p1[wid] = s1; p2[wid] = s2; }
    __syncthreads();
    if (c == 0) {
        float t1 = p1[0] + p1[1] + p1[2];
        float t2 = p2[0] + p2[1] + p2[2];
        float mean = t1 / 96.f;
        float var  = t2 / 96.f - mean * mean;
        mv[0] = mean; mv[1] = rsqrtf(var + 1e-5f);
    }
    __syncthreads();
    return (val - mv[0]) * mv[1] * gg[c] + bb[c];
}

// ---------------- Q pool (unchanged) ----------------
__global__ void pool_q_kernel(const float* __restrict__ cw, const float* __restrict__ gg,
                              const float* __restrict__ bb, int nSpatial)
{
    __shared__ float p1[3], p2[3], mv[2];
    int o = blockIdx.x;
    int c = threadIdx.x;

    if (o >= nSpatial) {
        int idx = o - nSpatial;
        int head = idx & 1, b = idx >> 1;
        float val = g_q[((size_t)b * N_IN) * 192 + head * 96 + c];
        float outv = ln96(val, gg, bb, c, p1, p2, mv);
        g_qp[((size_t)((b * 2 + head) * QN)) * 96 + c] = outv;
        return;
    }

    int w2 = o % QW;
    int h2 = (o / QW) % QH;
    int head = (o / (QW * QH)) & 1;
    int b = o / (QW * QH * 2);

    float wreg[27];
    #pragma unroll
    for (int t = 0; t < 27; ++t) wreg[t] = cw[c * 27 + t];

    float ps[8][3];
    #pragma unroll
    for (int it = 0; it < 8; ++it)
        #pragma unroll
        for (int d = 0; d < 3; ++d) ps[it][d] = 0.f;

    const float* base = g_q + ((size_t)(b * N_IN + 1)) * 192 + head * 96 + c;
    #pragma unroll
    for (int dh = 0; dh < 3; ++dh) {
        int ih = 2 * h2 - 1 + dh;
        if (ih < 0 || ih >= H_IN) continue;
        #pragma unroll
        for (int dw = 0; dw < 3; ++dw) {
            int iw = 2 * w2 - 1 + dw;
            if (iw < 0 || iw >= W_IN) continue;
            float w0 = wreg[(0 * 3 + dh) * 3 + dw];
            float w1 = wreg[(1 * 3 + dh) * 3 + dw];
            float w2r = wreg[(2 * 3 + dh) * 3 + dw];
            #pragma unroll
            for (int it = 0; it < 8; ++it) {
                int tok = (it * H_IN + ih) * W_IN + iw;
                float v = base[(size_t)tok * 192];
                ps[it][0] = fmaf(w0, v, ps[it][0]);
                ps[it][1] = fmaf(w1, v, ps[it][1]);
                ps[it][2] = fmaf(w2r, v, ps[it][2]);
            }
        }
    }

    for (int t2 = 0; t2 < QT; ++t2) {
        float s = ps[t2][1];
        if (t2 > 0) s += ps[t2 - 1][0];
        if (t2 < 7) s += ps[t2 + 1][2];
        float outv = ln96(s, gg, bb, c, p1, p2, mv);
        int n = 1 + (t2 * QH + h2) * QW + w2;
        g_qp[((size_t)((b * 2 + head) * QN) + n) * 96 + c] = outv;
        __syncthreads();
    }
}

// ---------------- K/V pool + LN -> extended K' (128 cols) and split V ----------------
__global__ void pool_kv_kernel(const float* __restrict__ cwk, const float* __restrict__ ggk,
                               const float* __restrict__ bbk,
                               const float* __restrict__ cwv, const float* __restrict__ ggv,
                               const float* __restrict__ bbv)
{
    __shared__ float p1[3], p2[3], mv[2];
    int whichV = blockIdx.y;
    const float* cw = whichV ? cwv : cwk;
    const float* gg = whichV ? ggv : ggk;
    const float* bb = whichV ? bbv : bbk;
    int o    = blockIdx.x;
    int n    = o % KNP;
    int head = (o / KNP) & 1;
    int b    = o / (KNP * 2);
    int c    = threadIdx.x;
    int bh   = b * 2 + head;

    if (n >= KN) {
        if (whichV) return;
        // padded K' row: channels 0, mask col (idx 22 -> col 118) = 1
        size_t rb = ((size_t)bh * KNP + n) * 128;
        __nv_bfloat16 z = __float2bfloat16(0.f);
        g_keh[rb + c] = z; g_kel[rb + c] = z;
        if (c < 32) {
            g_keh[rb + 96 + c] = __float2bfloat16((c == 22) ? 1.f : 0.f);
            g_kel[rb + 96 + c] = z;
        }
        return;
    }

    const float* src = whichV ? g_v : g_k;
    float val;
    if (n == 0) {
        val = src[((size_t)b * NKV) * 192 + head * 96 + c];
    } else {
        int tn  = n - 1;
        int t2  = tn / (KH * KW);
        int rem = tn % (KH * KW);
        int h2  = rem / KW, w2 = rem % KW;
        float s = 0.f;
        #pragma unroll
        for (int dt = 0; dt < 3; ++dt) {
            int it = t2 + dt - 1;
            if (it < 0 || it >= T_IN) continue;
            #pragma unroll
            for (int dh = 0; dh < 3; ++dh) {
                int ih = h2 * 8 + dh - 1;
                if (ih < 0 || ih >= H_IN) continue;
                #pragma unroll
                for (int dw = 0; dw < 3; ++dw) {
                    int iw = w2 * 8 + dw - 1;
                    if (iw < 0 || iw >= W_IN) continue;
                    int hi2 = (ih <= 1) ? ih : 2 + ((ih - 7) >> 3) * 3 + ((ih - 7) & 7);
                    int wi2 = (iw <= 1) ? iw : 2 + ((iw - 7) >> 3) * 3 + ((iw - 7) & 7);
                    int ci = 1 + (it * 20 + hi2) * 20 + wi2;
                    s = fmaf(cw[c * 27 + (dt * 3 + dh) * 3 + dw],
                             src[((size_t)(b * NKV + ci)) * 192 + head * 96 + c], s);
                }
            }
        }
        val = s;
    }
    float outv = ln96(val, gg, bb, c, p1, p2, mv);
    __nv_bfloat16 h = __float2bfloat16(outv);
    __nv_bfloat16 l = __float2bfloat16(outv - __bfloat162float(h));
    if (whichV) {
        size_t oidx = ((size_t)bh * KN + n) * 96 + c;
        g_vph[oidx] = h; g_vpl[oidx] = l;
    } else {
        size_t rb = ((size_t)bh * KNP + n) * 128;
        g_keh[rb + c] = h; g_kel[rb + c] = l;
        if (c < 32) {
            float ev = 0.f;
            if (n > 0 && c < 22) {
                int kk = n - 1, kt = kk / 49, rm = kk % 49;
                int rh = rm / 7, rw = rm % 7;
                if (c == kt || c == 8 + rh || c == 15 + rw) ev = 1.f;
            }
            g_keh[rb + 96 + c] = __float2bfloat16(ev);
            g_kel[rb + 96 + c] = __float2bfloat16(0.f);
        }
    }
}

// ============================================================================
// FA2 attention with rel-pos folded into QK (K'=128) and packed fast exp
// ============================================================================
#define ASM_KH   0
#define ASM_KL   17408
#define ASM_VH   34816
#define ASM_VL   48128
#define ASM_SRX  61440
#define ATTN_SMEM2 78848

__global__ void __launch_bounds__(256) attn_fa2_kernel(
    const float* __restrict__ rph, const float* __restrict__ rpw,
    const float* __restrict__ rpt)
{
    extern __shared__ char sm[];
    float* Qf = (float*)sm;                    // [128][100] fp32, dies before chunk loop
    float* srx = (float*)(sm + ASM_SRX);       // [128][34]: 22 srel + mask(-50) + zeros
    u32 smb = smem_u32(sm);

    int tid = threadIdx.x;
    int warp = tid >> 5, lane = tid & 31;
    int gr = lane >> 2;
    int wr0 = warp * 16;
    int bh = blockIdx.y;
    int q0 = blockIdx.x * 128;
    const float* qp = g_qp + (size_t)bh * QN * 96;
    const __nv_bfloat16* keh = g_keh + (size_t)bh * KNP * 128;
    const __nv_bfloat16* kel = g_kel + (size_t)bh * KNP * 128;
    const __nv_bfloat16* vph = g_vph + (size_t)bh * KN * 96;
    const __nv_bfloat16* vpl = g_vpl + (size_t)bh * KN * 96;

    // ---- stage Q fp32 via cp.async ----
    #pragma unroll
    for (int k12 = 0; k12 < 12; ++k12) {
        int l = tid + k12 * 256;
        int row = l / 24, seg = l - row * 24;
        int qr = q0 + row;
        u32 dst = smb + (u32)row * 400u + (u32)seg * 16u;
        cpa16(dst, qp + (size_t)qr * 96 + seg * 4, (qr < QN) ? 16 : 0);
    }
    CP_COMMIT();
    CP_WAIT0();
    __syncthreads();

    // ---- rel-pos dots + extension fills into srx ----
    for (int idx = tid; idx < 128 * 22; idx += 256) {
        int qi = idx / 22, r = idx - qi * 22;
        int qr = q0 + qi;
        float s = 0.f;
        if (qr > 0 && qr < QN) {
            int tok = qr - 1;
            int tq = tok / (QH * QW);
            int hq = (tok / QW) % QH;
            int wq = tok % QW;
            const float* tab;
            if (r < 8)       tab = rpt + (size_t)(tq - r + 7) * 96;
            else if (r < 15) tab = rph + (size_t)(hq - 4 * (r - 8) + 24) * 96;
            else             tab = rpw + (size_t)(wq - 4 * (r - 15) + 24) * 96;
            #pragma unroll 4
            for (int k = 0; k < 96; ++k) s = fmaf(Qf[qi * 100 + k], tab[k], s);
        }
        srx[qi * 34 + r] = s;
    }
    for (int l = tid; l < 128 * 10; l += 256) {
        int qi = l / 10, cidx = 22 + l - (l / 10) * 10;
        srx[qi * 34 + cidx] = (cidx == 22) ? -50.f : 0.f;
    }
    __syncthreads();

    // ---- Q' a-fragments (hi/lo): ks 0-5 = scale*q, ks 6-7 = srel extension ----
    u32 qh[8][4], ql[8][4];
    {
        int rA = wr0 + gr;
        int c2 = 2 * (lane & 3);
        #pragma unroll
        for (int ks = 0; ks < 6; ++ks) {
            int kb = ks * 16;
            float2 v0 = *(const float2*)&Qf[rA * 100 + kb + c2];
            float2 v1 = *(const float2*)&Qf[(rA + 8) * 100 + kb + c2];
            float2 v2 = *(const float2*)&Qf[rA * 100 + kb + 8 + c2];
            float2 v3 = *(const float2*)&Qf[(rA + 8) * 100 + kb + 8 + c2];
            qh[ks][0] = pack_hi(v0.x * ATTN_SCALE, v0.y * ATTN_SCALE, ql[ks][0]);
            qh[ks][1] = pack_hi(v1.x * ATTN_SCALE, v1.y * ATTN_SCALE, ql[ks][1]);
            qh[ks][2] = pack_hi(v2.x * ATTN_SCALE, v2.y * ATTN_SCALE, ql[ks][2]);
            qh[ks][3] = pack_hi(v3.x * ATTN_SCALE, v3.y * ATTN_SCALE, ql[ks][3]);
        }
        #pragma unroll
        for (int ks = 6; ks < 8; ++ks) {
            int base = (ks - 6) * 16;
            float a0 = srx[rA * 34 + base + c2],       a1 = srx[rA * 34 + base + c2 + 1];
            float b0 = srx[(rA + 8) * 34 + base + c2], b1 = srx[(rA + 8) * 34 + base + c2 + 1];
            float d0 = srx[rA * 34 + base + 8 + c2],   d1 = srx[rA * 34 + base + 8 + c2 + 1];
            float e0 = srx[(rA + 8) * 34 + base + 8 + c2], e1 = srx[(rA + 8) * 34 + base + 8 + c2 + 1];
            qh[ks][0] = pack_hi(a0, a1, ql[ks][0]);
            qh[ks][1] = pack_hi(b0, b1, ql[ks][1]);
            qh[ks][2] = pack_hi(d0, d1, ql[ks][2]);
            qh[ks][3] = pack_hi(e0, e1, ql[ks][3]);
        }
    }

    int qrA = q0 + wr0 + gr;
    int qrB = qrA + 8;

    float O[12][4];
    #pragma unroll
    for (int nt = 0; nt < 12; ++nt)
        #pragma unroll
        for (int i = 0; i < 4; ++i) O[nt][i] = 0.f;
    u64 sumA2 = 0ull, sumB2 = 0ull;

    for (int ch = 0; ch < 7; ++ch) {
        int j0 = ch * 64;
        __syncthreads();
        // stage K' (128 cols, stride 272B) and V (96 cols, stride 208B)
        #pragma unroll
        for (int k8 = 0; k8 < 8; ++k8) {
            int l = tid + k8 * 256;
            int buf = l >> 10, rem = l & 1023;
            int row = rem >> 4, seg = rem & 15;
            u32 dst = smb + (u32)buf * 17408u + (u32)row * 272u + (u32)seg * 16u;
            const __nv_bfloat16* s0 = buf ? kel : keh;
            cpa16(dst, s0 + ((size_t)(j0 + row)) * 128 + seg * 8, 16);
        }
        #pragma unroll
        for (int k6 = 0; k6 < 6; ++k6) {
            int l = tid + k6 * 256;
            int buf = l / 768, rem = l - buf * 768;
            int row = rem / 12, seg = rem - row * 12;
            int j = j0 + row;
            u32 dst = smb + ASM_VH + (u32)buf * 13312u + (u32)row * 208u + (u32)seg * 16u;
            cpa16(dst, (buf ? vpl : vph) + (size_t)j * 96 + seg * 8, (j < KN) ? 16 : 0);
        }
        CP_COMMIT();
        CP_WAIT0();
        __syncthreads();

        // ---- Q'K'^T -> finished scores ----
        float S[8][4];
        #pragma unroll
        for (int jt = 0; jt < 8; ++jt)
            #pragma unroll
            for (int i = 0; i < 4; ++i) S[jt][i] = 0.f;

        #pragma unroll
        for (int ks = 0; ks < 8; ++ks) {
            #pragma unroll
            for (int jt2 = 0; jt2 < 4; ++jt2) {
                u32 addr = smb + ASM_KH
                         + (u32)(jt2 * 16 + ((lane >> 4) << 3) + (lane & 7)) * 272u
                         + (u32)(ks * 16 + ((lane >> 3) & 1) * 8) * 2u;
                u32 bh4[4], bl4[4];
                ldm_x4(bh4, addr);
                ldm_x4(bl4, addr + (ASM_KL - ASM_KH));
                mma_bf16(S[2 * jt2],     qh[ks], bh4);
                mma_bf16(S[2 * jt2],     qh[ks], bl4);
                mma_bf16(S[2 * jt2],     ql[ks], bh4);
                mma_bf16(S[2 * jt2 + 1], qh[ks], bh4 + 2);
                mma_bf16(S[2 * jt2 + 1], qh[ks], bl4 + 2);
                mma_bf16(S[2 * jt2 + 1], ql[ks], bh4 + 2);
            }
        }

        // ---- packed fast exp (no guards needed: padded keys carry -50 bias) ----
        #pragma unroll
        for (int jt = 0; jt < 8; ++jt) {
            u64 eA = fexp2(S[jt][0], S[jt][1]);
            u64 eB = fexp2(S[jt][2], S[jt][3]);
            sumA2 = add2(sumA2, eA);
            sumB2 = add2(sumB2, eB);
            float2 fa = u2f(eA), fb = u2f(eB);
            S[jt][0] = fa.x; S[jt][1] = fa.y;
            S[jt][2] = fb.x; S[jt][3] = fb.y;
        }

        // ---- repack S as P a-fragments (hi/lo) ----
        u32 ph[4][4], pl[4][4];
        #pragma unroll
        for (int t = 0; t < 4; ++t) {
            ph[t][0] = pack_hi(S[2 * t][0],     S[2 * t][1],     pl[t][0]);
            ph[t][1] = pack_hi(S[2 * t][2],     S[2 * t][3],     pl[t][1]);
            ph[t][2] = pack_hi(S[2 * t + 1][0], S[2 * t + 1][1], pl[t][2]);
            ph[t][3] = pack_hi(S[2 * t + 1][2], S[2 * t + 1][3], pl[t][3]);
        }

        // ---- P @ V ----
        #pragma unroll
        for (int kt = 0; kt < 4; ++kt) {
            #pragma unroll
            for (int nt2 = 0; nt2 < 6; ++nt2) {
                u32 addr = smb + ASM_VH
                         + (u32)(kt * 16 + ((lane >> 3) & 1) * 8 + (lane & 7)) * 208u
                         + (u32)(nt2 * 16 + ((lane >> 4) << 3)) * 2u;
                u32 vh4[4], vl4[4];
                ldm_x4t(vh4, addr);
                ldm_x4t(vl4, addr + (ASM_VL - ASM_VH));
                mma_bf16(O[2 * nt2],     ph[kt], vh4);
                mma_bf16(O[2 * nt2],     ph[kt], vl4);
                mma_bf16(O[2 * nt2],     pl[kt], vh4);
                mma_bf16(O[2 * nt2 + 1], ph[kt], vh4 + 2);
                mma_bf16(O[2 * nt2 + 1], ph[kt], vl4 + 2);
                mma_bf16(O[2 * nt2 + 1], pl[kt], vh4 + 2);
            }
        }
    }

    // ---- row sums: horizontal + quad reduce ----
    float2 sa = u2f(sumA2), sb = u2f(sumB2);
    float sumA = sa.x + sa.y;
    float sumB = sb.x + sb.y;
    sumA += __shfl_xor_sync(0xffffffffu, sumA, 1);
    sumA += __shfl_xor_sync(0xffffffffu, sumA, 2);
    sumB += __shfl_xor_sync(0xffffffffu, sumB, 1);
    sumB += __shfl_xor_sync(0xffffffffu, sumB, 2);
    float riA = 1.f / sumA;
    float riB = 1.f / sumB;

    // ---- epilogue: normalize + residual + store as bf16 hi/lo ----
    int b = bh >> 1, head = bh & 1;
    int c2 = 2 * (lane & 3);
    if (qrA < QN) {
        #pragma unroll
        for (int nt = 0; nt < 12; ++nt) {
            int col = nt * 8 + c2;
            float2 qv = *(const float2*)&qp[(size_t)qrA * 96 + col];
            float2 o = make_float2(O[nt][0] * riA + qv.x, O[nt][1] * riA + qv.y);
            split_store(g_aoh, g_aol,
                        ((size_t)(b * QN + qrA)) * 192 + head * 96 + col, o);
        }
    }
    if (qrB < QN) {
        #pragma unroll
        for (int nt = 0; nt < 12; ++nt) {
            int col = nt * 8 + c2;
            float2 qv = *(const float2*)&qp[(size_t)qrB * 96 + col];
            float2 o = make_float2(O[nt][2] * riB + qv.x, O[nt][3] * riB + qv.y);
            split_store(g_aoh, g_aol,
                        ((size_t)(b * QN + qrB)) * 192 + head * 96 + col, o);
        }
    }
}

// ---------------- launch ----------------
extern "C" void kernel_launch(void* const* d_in, const int* in_sizes, int n_in,
                              void* d_out, int out_size)
{
    const float* x      = (const float*)d_in[0];
    const float* qkv_w  = (const float*)d_in[1];
    const float* qkv_b  = (const float*)d_in[2];
    const float* proj_w = (const float*)d_in[3];
    const float* proj_b = (const float*)d_in[4];
    const float* pq_w   = (const float*)d_in[5];
    const float* nq_g   = (const float*)d_in[6];
    const float* nq_b   = (const float*)d_in[7];
    const float* pk_w   = (const float*)d_in[8];
    const float* nk_g   = (const float*)d_in[9];
    const float* nk_b   = (const float*)d_in[10];
    const float* pv_w   = (const float*)d_in[11];
    const float* nv_g   = (const float*)d_in[12];
    const float* nv_b   = (const float*)d_in[13];
    const float* rph    = (const float*)d_in[14];
    const float* rpw    = (const float*)d_in[15];
    const float* rpt    = (const float*)d_in[16];

    int B = in_sizes[0] / (N_IN * 96);
    if (B > B_MAX) B = B_MAX;
    int M   = B * N_IN;
    int Mkv = B * NKV;
    int nbQ  = (M + 127) / 128;
    int nbKV = (Mkv + 127) / 128;

    cudaFuncSetAttribute(gemm_bf16, cudaFuncAttributeMaxDynamicSharedMemorySize, GEMM_SMEM);
    cudaFuncSetAttribute(attn_fa2_kernel, cudaFuncAttributeMaxDynamicSharedMemorySize, ATTN_SMEM2);

    int nx = M * 48;
    int totalPairs = nx + 576 * 96 / 2 + 192 * 192 / 2;
    presplit_kernel<<<(totalPairs + 255) / 256, 256>>>(x, qkv_w, proj_w, nx);

    gemm_bf16<<<nbQ + 2 * nbKV, 256, GEMM_SMEM>>>(qkv_b, nullptr, M, Mkv, 96, nbQ, nbKV, 1);

    int nSpatial = B * 2 * QH * QW;
    pool_q_kernel<<<nSpatial + B * 2, 96>>>(pq_w, nq_g, nq_b, nSpatial);
    pool_kv_kernel<<<dim3(B * 2 * KNP, 2), 96>>>(pk_w, nk_g, nk_b, pv_w, nv_g, nv_b);
    attn_fa2_kernel<<<dim3((QN + 127) / 128, B * 2), 256, ATTN_SMEM2>>>(rph, rpw, rpt);

    gemm_bf16<<<(B * QN + 127) / 128, 256, GEMM_SMEM>>>(proj_b, (float*)d_out,
                                                        B * QN, 0, 192, 0, 0, 0);
}